// round 10
// baseline (speedup 1.0000x reference)
#include <cuda_runtime.h>
#include <cuda_bf16.h>
#include <cstdint>
#include <math.h>

#define B_  4
#define N_  2048
#define D_  512
#define H_  8
#define E_  4
#define MT  (B_*N_)

__device__ float g_probs[MT*E_];
__device__ int   g_dtok[MT];
__device__ int   g_assigned[MT];
__device__ int   g_perm[MT];
__device__ float g_rp[MT];
__device__ float g_z [MT*D_];
__device__ float g_fpart[4][B_*512*512];
__device__ __nv_bfloat16 g_h_ext  [MT*1536];
__device__ __nv_bfloat16 g_o_ext  [MT*1536];
__device__ __nv_bfloat16 g_hm_ext [MT*1536];
__device__ __nv_bfloat16 g_hid_ext[(size_t)MT*6144];   // permuted rows
__device__ __nv_bfloat16 g_qext[(size_t)B_*H_*N_*192];
__device__ __nv_bfloat16 g_kext[(size_t)B_*H_*N_*192];
__device__ __nv_bfloat16 g_vh [(size_t)B_*H_*N_*64];
__device__ __nv_bfloat16 g_vl [(size_t)B_*H_*N_*64];
__device__ __nv_bfloat16 g_wqkv_ext[1536*1536];
__device__ __nv_bfloat16 g_wo_ext  [1536*512];
__device__ __nv_bfloat16 g_w1_ext  [1536*2048];
__device__ __nv_bfloat16 g_w2_ext  [6144*512];

__constant__ int c_head[80] = {
    0,0,0,0,0,0,0,0,0,0,0,0,0,0,0,0,0,0,0,0,0,0,0,0,0,0,0,0,0,0,0,0,
    1,1,1,1,1,1,1,1,1,1,1,1,1,1,1,1,
    2,2,2,2,2,2,2,2, 3,3,3,3,3,3,3,3,
    4,4,4,4, 5,5,5,5, 6,6,6,6, 7,7,7,7};
__constant__ int c_chunk[80] = {
    0,1,2,3,4,5,6,7,8,9,10,11,12,13,14,15,16,17,18,19,20,21,22,23,24,25,26,27,28,29,30,31,
    0,1,2,3,4,5,6,7,8,9,10,11,12,13,14,15,
    0,1,2,3,4,5,6,7, 0,1,2,3,4,5,6,7,
    0,1,2,3, 0,1,2,3, 0,1,2,3, 0,1,2,3};

__device__ __forceinline__ void bsplit(float v, __nv_bfloat16& h, __nv_bfloat16& l) {
    h = __float2bfloat16(v);
    l = __float2bfloat16(v - __bfloat162float(h));
}
__device__ __forceinline__ uint32_t packb(__nv_bfloat16 a, __nv_bfloat16 b) {
    __nv_bfloat162 t; t.x = a; t.y = b; return *(uint32_t*)&t;
}

__global__ void router_kernel(const float* __restrict__ x,
                              const float* __restrict__ rw,
                              const float* __restrict__ rb) {
    int warp = threadIdx.x >> 5, lane = threadIdx.x & 31;
    int t = blockIdx.x * 8 + warp;
    const float* xr = x + t * D_;
    double a0 = 0, a1 = 0, a2 = 0, a3 = 0;
    for (int j = lane; j < D_; j += 32) {
        double xv = (double)xr[j];
        const float* w = rw + j * E_;
        a0 += xv * (double)w[0]; a1 += xv * (double)w[1];
        a2 += xv * (double)w[2]; a3 += xv * (double)w[3];
    }
    #pragma unroll
    for (int o = 16; o > 0; o >>= 1) {
        a0 += __shfl_down_sync(0xffffffffu, a0, o);
        a1 += __shfl_down_sync(0xffffffffu, a1, o);
        a2 += __shfl_down_sync(0xffffffffu, a2, o);
        a3 += __shfl_down_sync(0xffffffffu, a3, o);
    }
    if (lane == 0) {
        double l0 = a0 + (double)rb[0], l1 = a1 + (double)rb[1];
        double l2 = a2 + (double)rb[2], l3 = a3 + (double)rb[3];
        double mx = fmax(fmax(l0, l1), fmax(l2, l3));
        double e0 = exp(l0 - mx), e1 = exp(l1 - mx), e2 = exp(l2 - mx), e3 = exp(l3 - mx);
        double s = e0 + e1 + e2 + e3;
        float* p = g_probs + t * 4;
        p[0] = (float)(e0 / s); p[1] = (float)(e1 / s);
        p[2] = (float)(e2 / s); p[3] = (float)(e3 / s);
    }
}

__device__ __forceinline__ unsigned int f2ord(float f) {
    unsigned int u = __float_as_uint(f);
    return (u & 0x80000000u) ? ~u : (u | 0x80000000u);
}

__global__ __launch_bounds__(1024) void assign_kernel() {
    const int b = blockIdx.x, tid = threadIdx.x;
    __shared__ unsigned long long key[N_];
    __shared__ int sas[N_];
    __shared__ int cnt[4];
    sas[tid] = -1; sas[tid + 1024] = -1;
    if (tid < 4) cnt[tid] = 0;
    __syncthreads();
    const int capByE[4] = {1024, 512, 256, 256};
    for (int p = 0; p < 3; p++) {
        const int e = 3 - p, cap = capByE[e];
        #pragma unroll
        for (int ii = 0; ii < 2; ii++) {
            int i = tid + ii * 1024;
            float pr = (sas[i] < 0) ? g_probs[(b * N_ + i) * E_ + e] : -1.0f;
            key[i] = ((unsigned long long)f2ord(pr) << 32) | (unsigned int)(0xFFFFFFFFu - (unsigned)i);
        }
        __syncthreads();
        for (int k = 2; k <= N_; k <<= 1) {
            for (int j = k >> 1; j > 0; j >>= 1) {
                #pragma unroll
                for (int ii = 0; ii < 2; ii++) {
                    int i = tid + ii * 1024, ixj = i ^ j;
                    if (ixj > i) {
                        unsigned long long a = key[i], c = key[ixj];
                        bool sw = ((i & k) == 0) ? (a < c) : (a > c);
                        if (sw) { key[i] = c; key[ixj] = a; }
                    }
                }
                __syncthreads();
            }
        }
        #pragma unroll
        for (int ii = 0; ii < 2; ii++) {
            int pos = tid + ii * 1024;
            if (pos < cap) {
                unsigned long long kk = key[pos];
                if ((unsigned int)(kk >> 32) >= 0x80000000u)
                    sas[(int)(0xFFFFFFFFu - (unsigned int)(kk & 0xFFFFFFFFu))] = e;
            }
        }
        __syncthreads();
    }
    const int startE[4] = {1024, 512, 256, 0};
    #pragma unroll
    for (int ii = 0; ii < 2; ii++) {
        int i = tid + ii * 1024;
        int a = sas[i]; if (a < 0) a = 0;
        int gi = b * N_ + i;
        g_assigned[gi] = a;
        g_dtok[gi] = 64 << a;
        g_rp[gi] = g_probs[gi * E_ + a];
        int pos = startE[a] + atomicAdd(&cnt[a], 1);
        g_perm[b * N_ + pos] = i;
    }
}

// ln; PASS 1 also writes out's masked cols (= z) so prepout launch is fused away
template<int PASS>
__global__ __launch_bounds__(256) void ln_kernel(const float* __restrict__ xin,
                                                 const float* __restrict__ gam,
                                                 const float* __restrict__ bet,
                                                 float* __restrict__ outp) {
    const int t = blockIdx.x;
    const float* r = (PASS == 0 ? xin : g_z) + t * D_;
    const int tid = threadIdx.x, lane = tid & 31, wid = tid >> 5;
    __shared__ float red[8];
    __shared__ float s_mu, s_rstd;
    float x0 = r[tid], x1 = r[tid + 256];
    float s = x0 + x1;
    #pragma unroll
    for (int o = 16; o > 0; o >>= 1) s += __shfl_down_sync(0xffffffffu, s, o);
    if (lane == 0) red[wid] = s;
    __syncthreads();
    if (tid == 0) {
        float tt = 0;
        #pragma unroll
        for (int w = 0; w < 8; w++) tt += red[w];
        s_mu = tt * (1.0f / 512.0f);
    }
    __syncthreads();
    float mu = s_mu;
    float d0 = x0 - mu, d1 = x1 - mu;
    float q = d0 * d0 + d1 * d1;
    #pragma unroll
    for (int o = 16; o > 0; o >>= 1) q += __shfl_down_sync(0xffffffffu, q, o);
    if (lane == 0) red[wid] = q;
    __syncthreads();
    if (tid == 0) {
        float tt = 0;
        #pragma unroll
        for (int w = 0; w < 8; w++) tt += red[w];
        s_rstd = rsqrtf(tt * (1.0f / 512.0f) + 1e-5f);
    }
    __syncthreads();
    float rstd = s_rstd;
    int dt = g_dtok[t];
    float y0 = (tid < dt)       ? (d0 * rstd * gam[tid]       + bet[tid])       : 0.0f;
    float y1 = (tid + 256 < dt) ? (d1 * rstd * gam[tid + 256] + bet[tid + 256]) : 0.0f;
    __nv_bfloat16 h0, l0, h1, l1;
    bsplit(y0, h0, l0); bsplit(y1, h1, l1);
    __nv_bfloat16* e = (PASS == 0 ? g_h_ext : g_hm_ext) + (size_t)t * 1536;
    e[tid]        = h0; e[tid + 512]        = h0; e[tid + 1024]        = l0;
    e[tid + 256]  = h1; e[tid + 256 + 512]  = h1; e[tid + 256 + 1024]  = l1;
    if (PASS == 1) {
        if (tid >= dt)       outp[(size_t)t * 512 + tid]       = x0;
        if (tid + 256 >= dt) outp[(size_t)t * 512 + tid + 256] = x1;
    }
}

// fused weight conversion: all 4 weights in one launch
__global__ void wconv_all_kernel(const float* __restrict__ wqkv,
                                 const float* __restrict__ wo,
                                 const float* __restrict__ w1,
                                 const float* __restrict__ w2) {
    int i = blockIdx.x * 256 + threadIdx.x;
    const float* src; __nv_bfloat16* ext; int total, off;
    if (i < 786432)       { src = wqkv; ext = g_wqkv_ext; total = 786432;  off = i; }
    else if (i < 1048576) { src = wo;   ext = g_wo_ext;   total = 262144;  off = i - 786432; }
    else if (i < 2097152) { src = w1;   ext = g_w1_ext;   total = 1048576; off = i - 1048576; }
    else                  { src = w2;   ext = g_w2_ext;   total = 1048576; off = i - 2097152; }
    __nv_bfloat16 h, l;
    bsplit(src[off], h, l);
    ext[off] = h; ext[total + off] = l; ext[2 * total + off] = h;
}

__device__ __forceinline__ void mma16816(float* c, const uint32_t* a, const uint32_t* b) {
    asm volatile("mma.sync.aligned.m16n8k16.row.col.f32.bf16.bf16.f32 "
                 "{%0,%1,%2,%3},{%4,%5,%6,%7},{%8,%9},{%0,%1,%2,%3};"
                 : "+f"(c[0]), "+f"(c[1]), "+f"(c[2]), "+f"(c[3])
                 : "r"(a[0]), "r"(a[1]), "r"(a[2]), "r"(a[3]), "r"(b[0]), "r"(b[1]));
}

// ---------------- K-restricted QKV / O-proj GEMM (proven R9) ----------------
template<int EPI, int NC>   // EPI 0: QKV (NC=1536); EPI 1: O-proj (NC=512)
__global__ void __launch_bounds__(256, 2) tgk_kernel(const float* __restrict__ bias,
                                                     const float* __restrict__ resid) {
    const __nv_bfloat16* Aext = (EPI == 0) ? g_h_ext : g_o_ext;
    const __nv_bfloat16* Bext = (EPI == 0) ? g_wqkv_ext : g_wo_ext;

    const int tid = threadIdx.x, lane = tid & 31, wid = tid >> 5;
    const int y = blockIdx.y;
    const int b = y >> 4, seg = y & 15;
    int e, mt;
    if (seg < 2)      { e = 3; mt = seg; }
    else if (seg < 4) { e = 2; mt = seg - 2; }
    else if (seg < 8) { e = 1; mt = seg - 4; }
    else              { e = 0; mt = seg - 8; }
    const int d = 64 << e;
    const int ld = 6 + e;
    const int dm = d - 1;
    const int NS = (3 * d) >> 5;
    const int segstart = (e == 3) ? 0 : (e == 2) ? 256 : (e == 1) ? 512 : 1024;
    const int bn = blockIdx.x * 128;

    __shared__ __align__(16) unsigned char smA[2][128 * 64];
    __shared__ __align__(16) unsigned char smB[2][32 * 256];
    __shared__ int sT[128];
    if (tid < 128) sT[tid] = g_perm[b * 2048 + segstart + mt * 128 + tid];
    __syncthreads();

    const int rA0 = tid >> 2, cA = tid & 3, rA1 = rA0 + 64;
    const __nv_bfloat16* Ap0 = Aext + (size_t)(b * 2048 + sT[rA0]) * 1536 + cA * 8;
    const __nv_bfloat16* Ap1 = Aext + (size_t)(b * 2048 + sT[rA1]) * 1536 + cA * 8;
    const int oA0 = rA0 * 64 + ((cA ^ ((rA0 >> 1) & 3)) << 4);
    const int oA1 = rA1 * 64 + ((cA ^ ((rA1 >> 1) & 3)) << 4);
    const int rB0 = tid >> 4, cB = tid & 15, rB1 = rB0 + 16;
    const __nv_bfloat16* Bp0 = Bext + (size_t)rB0 * NC + bn + cB * 8;
    const __nv_bfloat16* Bp1 = Bext + (size_t)rB1 * NC + bn + cB * 8;
    const int oB0 = rB0 * 256 + ((cB ^ (rB0 & 7)) << 4);
    const int oB1 = rB1 * 256 + ((cB ^ (rB1 & 7)) << 4);

    const int wm = (wid >> 2) * 64;
    const int widn = wid & 3;

    float acc[4][4][4];
    #pragma unroll
    for (int i = 0; i < 4; i++)
        #pragma unroll
        for (int j = 0; j < 4; j++)
            #pragma unroll
            for (int k = 0; k < 4; k++) acc[i][j][k] = 0.0f;

    #define KSTAGE(buf, slab) { \
        int k0_ = (slab) * 32; int kb_ = ((k0_ >> ld) << 9) + (k0_ & dm); \
        uint32_t ba_ = (uint32_t)__cvta_generic_to_shared(smA[buf]); \
        uint32_t bb_ = (uint32_t)__cvta_generic_to_shared(smB[buf]); \
        asm volatile("cp.async.cg.shared.global [%0],[%1],16;\n" :: "r"(ba_ + oA0), "l"(Ap0 + kb_)); \
        asm volatile("cp.async.cg.shared.global [%0],[%1],16;\n" :: "r"(ba_ + oA1), "l"(Ap1 + kb_)); \
        asm volatile("cp.async.cg.shared.global [%0],[%1],16;\n" :: "r"(bb_ + oB0), "l"(Bp0 + (size_t)kb_ * NC)); \
        asm volatile("cp.async.cg.shared.global [%0],[%1],16;\n" :: "r"(bb_ + oB1), "l"(Bp1 + (size_t)kb_ * NC)); \
        asm volatile("cp.async.commit_group;\n"); }

    KSTAGE(0, 0);

    #pragma unroll 1
    for (int s = 0; s < NS; s++) {
        int cur = s & 1;
        if (s + 1 < NS) {
            KSTAGE(cur ^ 1, s + 1);
            asm volatile("cp.async.wait_group 1;\n");
        } else {
            asm volatile("cp.async.wait_group 0;\n");
        }
        __syncthreads();
        unsigned char* As = smA[cur];
        unsigned char* Bs = smB[cur];
        #pragma unroll
        for (int kk = 0; kk < 2; kk++) {
            uint32_t af[4][4], bfr[4][2];
            #pragma unroll
            for (int mi = 0; mi < 4; mi++) {
                int r = wm + mi * 16 + (lane & 7) + ((lane & 8) ? 8 : 0);
                int c = kk * 2 + ((lane & 16) ? 1 : 0);
                uint32_t sa = (uint32_t)__cvta_generic_to_shared(
                    As + r * 64 + ((c ^ ((r >> 1) & 3)) << 4));
                asm volatile("ldmatrix.sync.aligned.m8n8.x4.shared.b16 {%0,%1,%2,%3},[%4];"
                             : "=r"(af[mi][0]), "=r"(af[mi][1]), "=r"(af[mi][2]), "=r"(af[mi][3])
                             : "r"(sa));
            }
            #pragma unroll
            for (int np = 0; np < 2; np++) {
                int kr = kk * 16 + (lane & 7) + ((lane & 8) ? 8 : 0);
                int c = widn * 4 + np * 2 + ((lane & 16) ? 1 : 0);
                uint32_t sb = (uint32_t)__cvta_generic_to_shared(
                    Bs + kr * 256 + ((c ^ (kr & 7)) << 4));
                asm volatile("ldmatrix.sync.aligned.m8n8.x4.trans.shared.b16 {%0,%1,%2,%3},[%4];"
                             : "=r"(bfr[np * 2][0]), "=r"(bfr[np * 2][1]),
                               "=r"(bfr[np * 2 + 1][0]), "=r"(bfr[np * 2 + 1][1])
                             : "r"(sb));
            }
            #pragma unroll
            for (int mi = 0; mi < 4; mi++)
                #pragma unroll
                for (int ni = 0; ni < 4; ni++)
                    mma16816(acc[mi][ni], af[mi], bfr[ni]);
        }
        __syncthreads();
    }

    const int l4 = lane >> 2, l2 = (lane & 3) * 2;
    const int dt = d;
    #pragma unroll
    for (int mi = 0; mi < 4; mi++) {
        #pragma unroll
        for (int hh = 0; hh < 2; hh++) {
            int mrl = wm + mi * 16 + l4 + hh * 8;
            int tokv = sT[mrl];
            #pragma unroll
            for (int ni = 0; ni < 4; ni++) {
                int n = bn + widn * 32 + ni * 8 + l2;
                float v0 = acc[mi][ni][hh * 2 + 0];
                float v1 = acc[mi][ni][hh * 2 + 1];
                if (EPI == 0) {
                    int chunk = n >> 9, f = n & 511;
                    int head = f >> 6, dd = f & 63;
                    bool on = (f < dt);
                    float w0 = on ? v0 : 0.0f;
                    float w1 = on ? v1 : 0.0f;
                    __nv_bfloat16 hh0, ll0, hh1, ll1;
                    bsplit(w0, hh0, ll0); bsplit(w1, hh1, ll1);
                    __nv_bfloat162 hi2; hi2.x = hh0; hi2.y = hh1;
                    __nv_bfloat162 lo2; lo2.x = ll0; lo2.y = ll1;
                    size_t base = (size_t)((b * H_ + head) * N_ + tokv);
                    if (chunk == 0) {
                        __nv_bfloat16* p = g_qext + base * 192 + dd;
                        *(__nv_bfloat162*)(p)       = hi2;
                        *(__nv_bfloat162*)(p + 64)  = hi2;
                        *(__nv_bfloat162*)(p + 128) = lo2;
                    } else if (chunk == 1) {
                        __nv_bfloat16* p = g_kext + base * 192 + dd;
                        *(__nv_bfloat162*)(p)       = hi2;
                        *(__nv_bfloat162*)(p + 64)  = lo2;
                        *(__nv_bfloat162*)(p + 128) = hi2;
                    } else {
                        *(__nv_bfloat162*)(g_vh + base * 64 + dd) = hi2;
                        *(__nv_bfloat162*)(g_vl + base * 64 + dd) = lo2;
                    }
                } else {
                    size_t row = (size_t)(b * 2048 + tokv) * 512;
                    float w0 = v0 + bias[n];
                    float w1 = v1 + bias[n + 1];
                    if (n >= dt) w0 = 0.0f;
                    if (n + 1 >= dt) w1 = 0.0f;
                    const float2 xr = *(const float2*)(resid + row + n);
                    float2 o; o.x = xr.x + w0; o.y = xr.y + w1;
                    *(float2*)(g_z + row + n) = o;
                }
            }
        }
    }
    #undef KSTAGE
}

// ---------------- grouped FFN GEMMs (proven R8/R9) ----------------
template<int EPI>
__global__ void __launch_bounds__(256, 2) ggemm_kernel(const float* __restrict__ bias,
                                                       const float* __restrict__ alpha,
                                                       float* __restrict__ outp) {
    const __nv_bfloat16* Aext = (EPI == 2) ? g_hm_ext : g_hid_ext;
    const __nv_bfloat16* Bext = (EPI == 2) ? g_w1_ext : g_w2_ext;
    constexpr int NC  = (EPI == 2) ? 2048 : 512;
    constexpr int SEG = (EPI == 3) ? 2048 : 512;
    constexpr size_t AROW = 3 * SEG;
    constexpr int TN0v = (EPI == 2) ? 2 : 1;
    constexpr int TN1v = (EPI == 2) ? 4 : 1;
    constexpr int TN2v = (EPI == 2) ? 8 : 2;
    constexpr int TN3v = (EPI == 2) ? 16 : 4;
    constexpr int TS3v = (EPI == 3) ? 4 : 1;
    constexpr int TS2v = (EPI == 3) ? 2 : 1;
    constexpr int C3 = 2 * TN3v * TS3v, C2 = 2 * TN2v * TS2v, C1 = 4 * TN1v;

    const int tid = threadIdx.x, lane = tid & 31, wid = tid >> 5;
    const int b = blockIdx.y;
    int idx = blockIdx.x;
    int e, loc, TN, TS;
    if (idx < C3)                 { e = 3; loc = idx;                  TN = TN3v; TS = TS3v; }
    else if (idx < C3 + C2)       { e = 2; loc = idx - C3;             TN = TN2v; TS = TS2v; }
    else if (idx < C3 + C2 + C1)  { e = 1; loc = idx - (C3 + C2);      TN = TN1v; TS = 1; }
    else                          { e = 0; loc = idx - (C3 + C2 + C1); TN = TN0v; TS = 1; }
    const int mt = loc / (TN * TS);
    int rem = loc - mt * (TN * TS);
    const int nt = rem / TS;
    const int sp = rem - nt * TS;
    const int d = 64 << e;
    const int ld = ((EPI == 3) ? 8 : 6) + e;
    const int dm = (1 << ld) - 1;
    const int NStot = (3 << ld) >> 5;
    const int per = NStot / TS;
    const int slab0 = sp * per, slab1 = slab0 + per;
    const int segstart = (e == 0) ? 1024 : (e == 1) ? 512 : (e == 2) ? 256 : 0;

    __shared__ __align__(16) unsigned char smA[2][128 * 64];
    __shared__ __align__(16) unsigned char smB[2][32 * 256];
    __shared__ int sA[128], sT[128];
    if (tid < 128) {
        int pos = segstart + mt * 128 + tid;
        int pv = g_perm[b * 2048 + pos];
        sT[tid] = pv;
        sA[tid] = (EPI == 3) ? (b * 2048 + pos) : (b * 2048 + pv);
    }
    __syncthreads();

    const int rA0 = tid >> 2, cA = tid & 3, rA1 = rA0 + 64;
    const __nv_bfloat16* Ap0 = Aext + (size_t)sA[rA0] * AROW + cA * 8;
    const __nv_bfloat16* Ap1 = Aext + (size_t)sA[rA1] * AROW + cA * 8;
    const int oA0 = rA0 * 64 + ((cA ^ ((rA0 >> 1) & 3)) << 4);
    const int oA1 = rA1 * 64 + ((cA ^ ((rA1 >> 1) & 3)) << 4);
    const int rB0 = tid >> 4, cB = tid & 15, rB1 = rB0 + 16;
    const int bc = nt * 128 + cB * 8;
    const __nv_bfloat16* Bp0 = Bext + (size_t)rB0 * NC + bc;
    const __nv_bfloat16* Bp1 = Bext + (size_t)rB1 * NC + bc;
    const int oB0 = rB0 * 256 + ((cB ^ (rB0 & 7)) << 4);
    const int oB1 = rB1 * 256 + ((cB ^ (rB1 & 7)) << 4);

    const int wm = (wid >> 2) * 64;
    const int widn = wid & 3;

    float acc[4][4][4];
    #pragma unroll
    for (int i = 0; i < 4; i++)
        #pragma unroll
        for (int jx = 0; jx < 4; jx++)
            #pragma unroll
            for (int k = 0; k < 4; k++) acc[i][jx][k] = 0.0f;

    #define GSTAGE(buf, slab) { \
        int kk_ = (slab) * 32; int kb_ = ((kk_ >> ld) * SEG) + (kk_ & dm); \
        uint32_t ba_ = (uint32_t)__cvta_generic_to_shared(smA[buf]); \
        uint32_t bb_ = (uint32_t)__cvta_generic_to_shared(smB[buf]); \
        asm volatile("cp.async.cg.shared.global [%0],[%1],16;\n" :: "r"(ba_ + oA0), "l"(Ap0 + kb_)); \
        asm volatile("cp.async.cg.shared.global [%0],[%1],16;\n" :: "r"(ba_ + oA1), "l"(Ap1 + kb_)); \
        asm volatile("cp.async.cg.shared.global [%0],[%1],16;\n" :: "r"(bb_ + oB0), "l"(Bp0 + (size_t)kb_ * NC)); \
        asm volatile("cp.async.cg.shared.global [%0],[%1],16;\n" :: "r"(bb_ + oB1), "l"(Bp1 + (size_t)kb_ * NC)); \
        asm volatile("cp.async.commit_group;\n"); }

    GSTAGE(0, slab0);

    #pragma unroll 1
    for (int s = slab0; s < slab1; s++) {
        int cur = (s - slab0) & 1;
        if (s + 1 < slab1) {
            GSTAGE(cur ^ 1, s + 1);
            asm volatile("cp.async.wait_group 1;\n");
        } else {
            asm volatile("cp.async.wait_group 0;\n");
        }
        __syncthreads();
        unsigned char* As = smA[cur];
        unsigned char* Bs = smB[cur];
        #pragma unroll
        for (int kk = 0; kk < 2; kk++) {
            uint32_t af[4][4], bfr[4][2];
            #pragma unroll
            for (int mi = 0; mi < 4; mi++) {
                int r = wm + mi * 16 + (lane & 7) + ((lane & 8) ? 8 : 0);
                int c = kk * 2 + ((lane & 16) ? 1 : 0);
                uint32_t sa = (uint32_t)__cvta_generic_to_shared(
                    As + r * 64 + ((c ^ ((r >> 1) & 3)) << 4));
                asm volatile("ldmatrix.sync.aligned.m8n8.x4.shared.b16 {%0,%1,%2,%3},[%4];"
                             : "=r"(af[mi][0]), "=r"(af[mi][1]), "=r"(af[mi][2]), "=r"(af[mi][3])
                             : "r"(sa));
            }
            #pragma unroll
            for (int np = 0; np < 2; np++) {
                int kr = kk * 16 + (lane & 7) + ((lane & 8) ? 8 : 0);
                int c = widn * 4 + np * 2 + ((lane & 16) ? 1 : 0);
                uint32_t sb = (uint32_t)__cvta_generic_to_shared(
                    Bs + kr * 256 + ((c ^ (kr & 7)) << 4));
                asm volatile("ldmatrix.sync.aligned.m8n8.x4.trans.shared.b16 {%0,%1,%2,%3},[%4];"
                             : "=r"(bfr[np * 2][0]), "=r"(bfr[np * 2][1]),
                               "=r"(bfr[np * 2 + 1][0]), "=r"(bfr[np * 2 + 1][1])
                             : "r"(sb));
            }
            #pragma unroll
            for (int mi = 0; mi < 4; mi++)
                #pragma unroll
                for (int ni = 0; ni < 4; ni++)
                    mma16816(acc[mi][ni], af[mi], bfr[ni]);
        }
        __syncthreads();
    }

    const int l4 = lane >> 2, l2 = (lane & 3) * 2;

    if (EPI == 3 && TS > 1) {
        #pragma unroll
        for (int mi = 0; mi < 4; mi++) {
            #pragma unroll
            for (int hh = 0; hh < 2; hh++) {
                int mrl = wm + mi * 16 + l4 + hh * 8;
                int pos = segstart + mt * 128 + mrl;
                #pragma unroll
                for (int ni = 0; ni < 4; ni++) {
                    int n = nt * 128 + widn * 32 + ni * 8 + l2;
                    float2 v; v.x = acc[mi][ni][hh * 2]; v.y = acc[mi][ni][hh * 2 + 1];
                    *(float2*)&g_fpart[sp][((b << 9) + pos) * 512 + n] = v;
                }
            }
        }
        return;
    }

    float aval = 0.0f;
    if (EPI == 3) aval = alpha[0];

    #pragma unroll
    for (int mi = 0; mi < 4; mi++) {
        #pragma unroll
        for (int hh = 0; hh < 2; hh++) {
            int mrl = wm + mi * 16 + l4 + hh * 8;
            int tok = sT[mrl];
            #pragma unroll
            for (int ni = 0; ni < 4; ni++) {
                int n = nt * 128 + widn * 32 + ni * 8 + l2;
                float v0 = acc[mi][ni][hh * 2 + 0];
                float v1 = acc[mi][ni][hh * 2 + 1];
                if (EPI == 2) {
                    if (n < 4 * d) {
                        int pos = segstart + mt * 128 + mrl;
                        size_t row = (size_t)(b * 2048 + pos) * 6144;
                        float w = v0 + bias[n];
                        float c1 = 0.7978845608028654f * (w + 0.044715f * w * w * w);
                        float h0 = 0.5f * w * (1.0f + tanhf(c1));
                        w = v1 + bias[n + 1];
                        c1 = 0.7978845608028654f * (w + 0.044715f * w * w * w);
                        float h1 = 0.5f * w * (1.0f + tanhf(c1));
                        __nv_bfloat16 a0, b0, a1, b1;
                        bsplit(h0, a0, b0); bsplit(h1, a1, b1);
                        __nv_bfloat162 hi; hi.x = a0; hi.y = a1;
                        __nv_bfloat162 lo; lo.x = b0; lo.y = b1;
                        *(__nv_bfloat162*)(g_hid_ext + row + n)        = hi;
                        *(__nv_bfloat162*)(g_hid_ext + row + n + 2048) = hi;
                        *(__nv_bfloat162*)(g_hid_ext + row + n + 4096) = lo;
                    }
                } else {
                    if (n < d) {
                        size_t row = (size_t)(b * 2048 + tok) * 512;
                        float gm = aval * g_rp[b * 2048 + tok] + 1.0f;
                        float w0 = v0 + bias[n];
                        float w1 = v1 + bias[n + 1];
                        const float2 zz = *(const float2*)(g_z + row + n);
                        float2 o; o.x = zz.x + gm * w0; o.y = zz.y + gm * w1;
                        *(float2*)(outp + row + n) = o;
                    }
                }
            }
        }
    }
    #undef GSTAGE
}

__global__ void reduce3_kernel(const float* __restrict__ b2f,
                               const float* __restrict__ alpha,
                               float* __restrict__ outp) {
    int rowid = blockIdx.x;
    int b = rowid >> 9, pos = rowid & 511;
    int ns = (pos < 256) ? 4 : 2;
    int d = (pos < 256) ? 512 : 256;
    int tok = g_perm[b * 2048 + pos];
    float gm = alpha[0] * g_rp[b * 2048 + tok] + 1.0f;
    size_t row = (size_t)(b * 2048 + tok) * 512;
    int base = ((b << 9) + pos) * 512;
    for (int n = threadIdx.x; n < d; n += 256) {
        float s = g_fpart[0][base + n] + g_fpart[1][base + n];
        if (ns == 4) s += g_fpart[2][base + n] + g_fpart[3][base + n];
        s += b2f[n];
        outp[row + n] = g_z[row + n] + gm * s;
    }
}

// ---------------- tensor-core flash attention, double-buffered K/V ----------------
// smem: Q 25600 + 2 stages x (K 25600 + Vh 9216 + Vl 9216) = 113664 B -> 2 CTAs/SM
__global__ void __launch_bounds__(128, 2) fattn_kernel() {
    const int b = blockIdx.y;
    const int slot = blockIdx.x;
    const int h = c_head[slot];
    const int ch = c_chunk[slot];
    extern __shared__ __align__(16) unsigned char sm[];
    unsigned char* Qs = sm;
    unsigned char* stage[2];
    stage[0] = sm + 25600;
    stage[1] = sm + 25600 + 44032;
    __shared__ int tok[64];
    const int tid = threadIdx.x, lane = tid & 31, wid = tid >> 5;

    if (tid < 64) tok[tid] = g_perm[b * N_ + ch * 64 + tid];
    __syncthreads();
    const size_t bh = (size_t)(b * H_ + h) * N_;

    // load Q (group 0) — then stage 0 of K/V (group 1)
    for (int i = tid; i < 64 * 24; i += 128) {
        int r = i / 24, c = i % 24;
        const __nv_bfloat16* g = g_qext + (bh + tok[r]) * 192 + c * 8;
        uint32_t s = (uint32_t)__cvta_generic_to_shared(Qs + r * 400 + c * 16);
        asm volatile("cp.async.cg.shared.global [%0],[%1],16;\n" :: "r"(s), "l"(g));
    }
    asm volatile("cp.async.commit_group;\n");

    #define KVLOAD(buf, k0v) { \
        unsigned char* Ks_ = stage[buf]; \
        unsigned char* Vhs_ = stage[buf] + 25600; \
        unsigned char* Vls_ = stage[buf] + 34816; \
        for (int i = tid; i < 64 * 24; i += 128) { \
            int r = i / 24, c = i % 24; \
            const __nv_bfloat16* g = g_kext + (bh + (k0v) + r) * 192 + c * 8; \
            uint32_t s = (uint32_t)__cvta_generic_to_shared(Ks_ + r * 400 + c * 16); \
            asm volatile("cp.async.cg.shared.global [%0],[%1],16;\n" :: "r"(s), "l"(g)); \
        } \
        for (int i = tid; i < 64 * 8; i += 128) { \
            int r = i / 8, c = i % 8; \
            const __nv_bfloat16* gh = g_vh + (bh + (k0v) + r) * 64 + c * 8; \
            const __nv_bfloat16* gl = g_vl + (bh + (k0v) + r) * 64 + c * 8; \
            uint32_t sh = (uint32_t)__cvta_generic_to_shared(Vhs_ + r * 144 + c * 16); \
            uint32_t sl = (uint32_t)__cvta_generic_to_shared(Vls_ + r * 144 + c * 16); \
            asm volatile("cp.async.cg.shared.global [%0],[%1],16;\n" :: "r"(sh), "l"(gh)); \
            asm volatile("cp.async.cg.shared.global [%0],[%1],16;\n" :: "r"(sl), "l"(gl)); \
        } \
        asm volatile("cp.async.commit_group;\n"); }

    KVLOAD(0, 0);

    float accO[8][4];
    #pragma unroll
    for (int i = 0; i < 8; i++)
        #pragma unroll
        for (int j = 0; j < 4; j++) accO[i][j] = 0.0f;
    float m0 = -3.0e38f, m1 = -3.0e38f, l0 = 0.0f, l1 = 0.0f;

    const int qrow = wid * 16 + (lane & 15);
    const int krow7 = (lane & 7) + ((lane & 16) ? 8 : 0);
    const int kcsel = ((lane & 8) ? 1 : 0);
    const int vrow7 = (lane & 7) + ((lane & 8) ? 8 : 0);
    const int vcsel = ((lane & 16) ? 1 : 0);

    #pragma unroll 1
    for (int it = 0; it < 32; it++) {
        int cur = it & 1;
        if (it + 1 < 32) {
            KVLOAD(cur ^ 1, (it + 1) * 64);
            asm volatile("cp.async.wait_group 1;\n");
        } else {
            asm volatile("cp.async.wait_group 0;\n");
        }
        __syncthreads();

        unsigned char* Ks  = stage[cur];
        unsigned char* Vhs = stage[cur] + 25600;
        unsigned char* Vls = stage[cur] + 34816;

        float S[8][4];
        #pragma unroll
        for (int i = 0; i < 8; i++)
            #pragma unroll
            for (int j = 0; j < 4; j++) S[i][j] = 0.0f;

        #pragma unroll
        for (int ks = 0; ks < 12; ks++) {
            uint32_t qf[4];
            uint32_t sa = (uint32_t)__cvta_generic_to_shared(
                Qs + qrow * 400 + (ks * 2 + (lane >> 4)) * 16);
            asm volatile("ldmatrix.sync.aligned.m8n8.x4.shared.b16 {%0,%1,%2,%3},[%4];"
                         : "=r"(qf[0]), "=r"(qf[1]), "=r"(qf[2]), "=r"(qf[3]) : "r"(sa));
            #pragma unroll
            for (int p = 0; p < 4; p++) {
                uint32_t kf[4];
                uint32_t sb = (uint32_t)__cvta_generic_to_shared(
                    Ks + (p * 16 + krow7) * 400 + (ks * 2 + kcsel) * 16);
                asm volatile("ldmatrix.sync.aligned.m8n8.x4.shared.b16 {%0,%1,%2,%3},[%4];"
                             : "=r"(kf[0]), "=r"(kf[1]), "=r"(kf[2]), "=r"(kf[3]) : "r"(sb));
                mma16816(S[2 * p],     qf, kf);
                mma16816(S[2 * p + 1], qf, kf + 2);
            }
        }

        float mx0 = -3.0e38f, mx1 = -3.0e38f;
        #pragma unroll
        for (int ni = 0; ni < 8; ni++) {
            S[ni][0] *= 0.125f; S[ni][1] *= 0.125f; S[ni][2] *= 0.125f; S[ni][3] *= 0.125f;
            mx0 = fmaxf(mx0, fmaxf(S[ni][0], S[ni][1]));
            mx1 = fmaxf(mx1, fmaxf(S[ni][2], S[ni][3]));
        }
        mx0 = fmaxf(mx0, __shfl_xor_sync(0xffffffffu, mx0, 1));
        mx0 = fmaxf(mx0, __shfl_xor_sync(0xffffffffu, mx0, 2));
        mx1 = fmaxf(mx1, __shfl_xor_sync(0xffffffffu, mx1, 1));
        mx1 = fmaxf(mx1, __shfl_xor_sync(0xffffffffu, mx1, 2));
        float mn0 = fmaxf(m0, mx0), mn1 = fmaxf(m1, mx1);
        float cr0 = __expf(m0 - mn0), cr1 = __expf(m1 - mn1);
        float s0 = 0.0f, s1 = 0.0f;
        uint32_t pha[8], phb[8], pla[8], plb[8];
        #pragma unroll
        for (int ni = 0; ni < 8; ni++) {
            float p00 = __expf(S[ni][0] - mn0), p01 = __expf(S[ni][1] - mn0);
            float p10 = __expf(S[ni][2] - mn1), p11 = __expf(S[ni][3] - mn1);
            s0 += p00 + p01; s1 += p10 + p11;
            __nv_bfloat16 h00, l00, h01, l01, h10, l10, h11, l11;
            bsplit(p00, h00, l00); bsplit(p01, h01, l01);
            bsplit(p10, h10, l10); bsplit(p11, h11, l11);
            pha[ni] = packb(h00, h01); phb[ni] = packb(h10, h11);
            pla[ni] = packb(l00, l01); plb[ni] = packb(l10, l11);
        }
        s0 += __shfl_xor_sync(0xffffffffu, s0, 1);
        s0 += __shfl_xor_sync(0xffffffffu, s0, 2);
        s1 += __shfl_xor_sync(0xffffffffu, s1, 1);
        s1 += __shfl_xor_sync(0xffffffffu, s1, 2);
        l0 = l0 * cr0 + s0; l1 = l1 * cr1 + s1;
        m0 = mn0; m1 = mn1;
        #pragma unroll
        for (int ni = 0; ni < 8; ni++) {
            accO[ni][0] *= cr0; accO[ni][1] *= cr0;
            accO[ni][2] *= cr1; accO[ni][3] *= cr1;
        }

        #pragma unroll
        for (int kt = 0; kt < 4; kt++) {
            uint32_t pa[4] = {pha[2 * kt], phb[2 * kt], pha[2 * kt + 1], phb[2 * kt + 1]};
            uint32_t la[4] = {pla[2 * kt], plb[2 * kt], pla[2 * kt + 1], plb[2 * kt + 1]};
            #pragma unroll
            for (int p = 0; p < 4; p++) {
                uint32_t vh[4], vl[4];
                uint32_t svh = (uint32_t)__cvta_generic_to_shared(
                    Vhs + (kt * 16 + vrow7) * 144 + (p * 2 + vcsel) * 16);
                uint32_t svl = (uint32_t)__cvta_generic_to_shared(
                    Vls + (kt * 16 + vrow7) * 144 + (p * 2 + vcsel) * 16);
                asm volatile("ldmatrix.sync.aligned.m8n8.x4.trans.shared.b16 {%0,%1,%2,%3},[%4];"
                             : "=r"(vh[0]), "=r"(vh[1]), "=r"(vh[2]), "=r"(vh[3]) : "r"(svh));
                asm volatile("ldmatrix.sync.aligned.m8n8.x4.trans.shared.b16 {%0,%1,%2,%3},[%4];"
                             : "=r"(vl[0]), "=r"(vl[1]), "=r"(vl[2]), "=r"(vl[3]) : "r"(svl));
                mma16816(accO[2 * p],     pa, vh);
                mma16816(accO[2 * p + 1], pa, vh + 2);
                mma16816(accO[2 * p],     pa, vl);
                mma16816(accO[2 * p + 1], pa, vl + 2);
                mma16816(accO[2 * p],     la, vh);
                mma16816(accO[2 * p + 1], la, vh + 2);
            }
        }
        __syncthreads();
    }
    #undef KVLOAD

    float inv0 = 1.0f / l0, inv1 = 1.0f / l1;
    const int ilo = wid * 16 + (lane >> 2);
    const int ihi = ilo + 8;
    const size_t rlo = (size_t)(b * N_ + tok[ilo]) * 1536 + h * 64 + (lane & 3) * 2;
    const size_t rhi = (size_t)(b * N_ + tok[ihi]) * 1536 + h * 64 + (lane & 3) * 2;
    #pragma unroll
    for (int ni = 0; ni < 8; ni++) {
        float o0 = accO[ni][0] * inv0, o1 = accO[ni][1] * inv0;
        float o2 = accO[ni][2] * inv1, o3 = accO[ni][3] * inv1;
        __nv_bfloat16 h0, q0, h1, q1, h2, q2, h3, q3;
        bsplit(o0, h0, q0); bsplit(o1, h1, q1);
        bsplit(o2, h2, q2); bsplit(o3, h3, q3);
        __nv_bfloat162 hiA; hiA.x = h0; hiA.y = h1;
        __nv_bfloat162 loA; loA.x = q0; loA.y = q1;
        __nv_bfloat162 hiB; hiB.x = h2; hiB.y = h3;
        __nv_bfloat162 loB; loB.x = q2; loB.y = q3;
        *(__nv_bfloat162*)(g_o_ext + rlo + ni * 8)        = hiA;
        *(__nv_bfloat162*)(g_o_ext + rlo + ni * 8 + 512)  = hiA;
        *(__nv_bfloat162*)(g_o_ext + rlo + ni * 8 + 1024) = loA;
        *(__nv_bfloat162*)(g_o_ext + rhi + ni * 8)        = hiB;
        *(__nv_bfloat162*)(g_o_ext + rhi + ni * 8 + 512)  = hiB;
        *(__nv_bfloat162*)(g_o_ext + rhi + ni * 8 + 1024) = loB;
    }
}

__global__ void extras_kernel(float* __restrict__ outp, int write_rp) {
    int i = blockIdx.x * 256 + threadIdx.x;
    if (i < MT) {
        outp[MT * D_ + i] = (float)g_assigned[i];
        if (write_rp) outp[MT * D_ + MT + i] = g_rp[i];
    }
}

extern "C" void kernel_launch(void* const* d_in, const int* in_sizes, int n_in,
                              void* d_out, int out_size) {
    const float* x     = (const float*)d_in[0];
    const float* r_w   = (const float*)d_in[1];
    const float* r_b   = (const float*)d_in[2];
    const float* g1    = (const float*)d_in[3];
    const float* b1    = (const float*)d_in[4];
    const float* g2    = (const float*)d_in[5];
    const float* b2    = (const float*)d_in[6];
    const float* w_qkv = (const float*)d_in[7];
    const float* w_o   = (const float*)d_in[8];
    const float* b_o   = (const float*)d_in[9];
    const float* w1    = (const float*)d_in[10];
    const float* b1f   = (const float*)d_in[11];
    const float* w2    = (const float*)d_in[12];
    const float* b2f   = (const float*)d_in[13];
    const float* alpha = (const float*)d_in[14];
    float* out = (float*)d_out;

    static const int FATTN_SMEM = 25600 + 2 * 44032;   // 113664
    cudaFuncSetAttribute(fattn_kernel, cudaFuncAttributeMaxDynamicSharedMemorySize, FATTN_SMEM);

    router_kernel<<<MT / 8, 256>>>(x, r_w, r_b);
    assign_kernel<<<B_, 1024>>>();
    wconv_all_kernel<<<3145728 / 256, 256>>>(w_qkv, w_o, w1, w2);

    ln_kernel<0><<<MT, 256>>>(x, g1, b1, nullptr);
    tgk_kernel<0, 1536><<<dim3(12, 64), 256>>>(nullptr, nullptr);
    fattn_kernel<<<dim3(80, B_), 128, FATTN_SMEM>>>();
    tgk_kernel<1, 512><<<dim3(4, 64), 256>>>(b_o, x);
    ln_kernel<1><<<MT, 256>>>(x, g2, b2, out);
    ggemm_kernel<2><<<dim3(80, B_), 256>>>(b1f, nullptr, nullptr);
    ggemm_kernel<3><<<dim3(52, B_), 256>>>(b2f, alpha, out);
    reduce3_kernel<<<B_ * 512, 256>>>(b2f, alpha, out);

    if (out_size >= MT * D_ + MT) {
        int write_rp = (out_size >= MT * D_ + 2 * MT) ? 1 : 0;
        extras_kernel<<<(MT + 255) / 256, 256>>>(out, write_rp);
    }
}

// round 11
// speedup vs baseline: 1.0245x; 1.0245x over previous
#include <cuda_runtime.h>
#include <cuda_bf16.h>
#include <cstdint>
#include <math.h>

#define B_  4
#define N_  2048
#define D_  512
#define H_  8
#define E_  4
#define MT  (B_*N_)

__device__ float g_probs[MT*E_];
__device__ int   g_dtok[MT];
__device__ int   g_assigned[MT];
__device__ int   g_perm[MT];
__device__ float g_rp[MT];
__device__ float g_z [MT*D_];
__device__ float g_fpart[4][B_*512*512];
__device__ __nv_bfloat16 g_h_ext  [MT*1536];
__device__ __nv_bfloat16 g_o_ext  [MT*1536];
__device__ __nv_bfloat16 g_hm_ext [MT*1536];
__device__ __nv_bfloat16 g_hid_ext[(size_t)MT*6144];   // permuted rows
__device__ __nv_bfloat16 g_qext[(size_t)B_*H_*N_*192];
__device__ __nv_bfloat16 g_kext[(size_t)B_*H_*N_*192];
__device__ __nv_bfloat16 g_vh [(size_t)B_*H_*N_*64];
__device__ __nv_bfloat16 g_vl [(size_t)B_*H_*N_*64];
__device__ __nv_bfloat16 g_wqkv_ext[1536*1536];
__device__ __nv_bfloat16 g_wo_ext  [1536*512];
__device__ __nv_bfloat16 g_w1_ext  [1536*2048];
__device__ __nv_bfloat16 g_w2_ext  [6144*512];

__constant__ int c_head[80] = {
    0,0,0,0,0,0,0,0,0,0,0,0,0,0,0,0,0,0,0,0,0,0,0,0,0,0,0,0,0,0,0,0,
    1,1,1,1,1,1,1,1,1,1,1,1,1,1,1,1,
    2,2,2,2,2,2,2,2, 3,3,3,3,3,3,3,3,
    4,4,4,4, 5,5,5,5, 6,6,6,6, 7,7,7,7};
__constant__ int c_chunk[80] = {
    0,1,2,3,4,5,6,7,8,9,10,11,12,13,14,15,16,17,18,19,20,21,22,23,24,25,26,27,28,29,30,31,
    0,1,2,3,4,5,6,7,8,9,10,11,12,13,14,15,
    0,1,2,3,4,5,6,7, 0,1,2,3,4,5,6,7,
    0,1,2,3, 0,1,2,3, 0,1,2,3, 0,1,2,3};

__device__ __forceinline__ void bsplit(float v, __nv_bfloat16& h, __nv_bfloat16& l) {
    h = __float2bfloat16(v);
    l = __float2bfloat16(v - __bfloat162float(h));
}
__device__ __forceinline__ uint32_t packb(__nv_bfloat16 a, __nv_bfloat16 b) {
    __nv_bfloat162 t; t.x = a; t.y = b; return *(uint32_t*)&t;
}

__global__ void router_kernel(const float* __restrict__ x,
                              const float* __restrict__ rw,
                              const float* __restrict__ rb) {
    int warp = threadIdx.x >> 5, lane = threadIdx.x & 31;
    int t = blockIdx.x * 8 + warp;
    const float* xr = x + t * D_;
    double a0 = 0, a1 = 0, a2 = 0, a3 = 0;
    for (int j = lane; j < D_; j += 32) {
        double xv = (double)xr[j];
        const float* w = rw + j * E_;
        a0 += xv * (double)w[0]; a1 += xv * (double)w[1];
        a2 += xv * (double)w[2]; a3 += xv * (double)w[3];
    }
    #pragma unroll
    for (int o = 16; o > 0; o >>= 1) {
        a0 += __shfl_down_sync(0xffffffffu, a0, o);
        a1 += __shfl_down_sync(0xffffffffu, a1, o);
        a2 += __shfl_down_sync(0xffffffffu, a2, o);
        a3 += __shfl_down_sync(0xffffffffu, a3, o);
    }
    if (lane == 0) {
        double l0 = a0 + (double)rb[0], l1 = a1 + (double)rb[1];
        double l2 = a2 + (double)rb[2], l3 = a3 + (double)rb[3];
        double mx = fmax(fmax(l0, l1), fmax(l2, l3));
        double e0 = exp(l0 - mx), e1 = exp(l1 - mx), e2 = exp(l2 - mx), e3 = exp(l3 - mx);
        double s = e0 + e1 + e2 + e3;
        float* p = g_probs + t * 4;
        p[0] = (float)(e0 / s); p[1] = (float)(e1 / s);
        p[2] = (float)(e2 / s); p[3] = (float)(e3 / s);
    }
}

__device__ __forceinline__ unsigned int f2ord(float f) {
    unsigned int u = __float_as_uint(f);
    return (u & 0x80000000u) ? ~u : (u | 0x80000000u);
}

__global__ __launch_bounds__(1024) void assign_kernel() {
    const int b = blockIdx.x, tid = threadIdx.x;
    __shared__ unsigned long long key[N_];
    __shared__ int sas[N_];
    __shared__ int cnt[4];
    sas[tid] = -1; sas[tid + 1024] = -1;
    if (tid < 4) cnt[tid] = 0;
    __syncthreads();
    const int capByE[4] = {1024, 512, 256, 256};
    for (int p = 0; p < 3; p++) {
        const int e = 3 - p, cap = capByE[e];
        #pragma unroll
        for (int ii = 0; ii < 2; ii++) {
            int i = tid + ii * 1024;
            float pr = (sas[i] < 0) ? g_probs[(b * N_ + i) * E_ + e] : -1.0f;
            key[i] = ((unsigned long long)f2ord(pr) << 32) | (unsigned int)(0xFFFFFFFFu - (unsigned)i);
        }
        __syncthreads();
        for (int k = 2; k <= N_; k <<= 1) {
            for (int j = k >> 1; j > 0; j >>= 1) {
                #pragma unroll
                for (int ii = 0; ii < 2; ii++) {
                    int i = tid + ii * 1024, ixj = i ^ j;
                    if (ixj > i) {
                        unsigned long long a = key[i], c = key[ixj];
                        bool sw = ((i & k) == 0) ? (a < c) : (a > c);
                        if (sw) { key[i] = c; key[ixj] = a; }
                    }
                }
                __syncthreads();
            }
        }
        #pragma unroll
        for (int ii = 0; ii < 2; ii++) {
            int pos = tid + ii * 1024;
            if (pos < cap) {
                unsigned long long kk = key[pos];
                if ((unsigned int)(kk >> 32) >= 0x80000000u)
                    sas[(int)(0xFFFFFFFFu - (unsigned int)(kk & 0xFFFFFFFFu))] = e;
            }
        }
        __syncthreads();
    }
    const int startE[4] = {1024, 512, 256, 0};
    #pragma unroll
    for (int ii = 0; ii < 2; ii++) {
        int i = tid + ii * 1024;
        int a = sas[i]; if (a < 0) a = 0;
        int gi = b * N_ + i;
        g_assigned[gi] = a;
        g_dtok[gi] = 64 << a;
        g_rp[gi] = g_probs[gi * E_ + a];
        int pos = startE[a] + atomicAdd(&cnt[a], 1);
        g_perm[b * N_ + pos] = i;
    }
}

// ln; PASS 1 also writes out's masked cols (= z) so prepout launch is fused away
template<int PASS>
__global__ __launch_bounds__(256) void ln_kernel(const float* __restrict__ xin,
                                                 const float* __restrict__ gam,
                                                 const float* __restrict__ bet,
                                                 float* __restrict__ outp) {
    const int t = blockIdx.x;
    const float* r = (PASS == 0 ? xin : g_z) + t * D_;
    const int tid = threadIdx.x, lane = tid & 31, wid = tid >> 5;
    __shared__ float red[8];
    __shared__ float s_mu, s_rstd;
    float x0 = r[tid], x1 = r[tid + 256];
    float s = x0 + x1;
    #pragma unroll
    for (int o = 16; o > 0; o >>= 1) s += __shfl_down_sync(0xffffffffu, s, o);
    if (lane == 0) red[wid] = s;
    __syncthreads();
    if (tid == 0) {
        float tt = 0;
        #pragma unroll
        for (int w = 0; w < 8; w++) tt += red[w];
        s_mu = tt * (1.0f / 512.0f);
    }
    __syncthreads();
    float mu = s_mu;
    float d0 = x0 - mu, d1 = x1 - mu;
    float q = d0 * d0 + d1 * d1;
    #pragma unroll
    for (int o = 16; o > 0; o >>= 1) q += __shfl_down_sync(0xffffffffu, q, o);
    if (lane == 0) red[wid] = q;
    __syncthreads();
    if (tid == 0) {
        float tt = 0;
        #pragma unroll
        for (int w = 0; w < 8; w++) tt += red[w];
        s_rstd = rsqrtf(tt * (1.0f / 512.0f) + 1e-5f);
    }
    __syncthreads();
    float rstd = s_rstd;
    int dt = g_dtok[t];
    float y0 = (tid < dt)       ? (d0 * rstd * gam[tid]       + bet[tid])       : 0.0f;
    float y1 = (tid + 256 < dt) ? (d1 * rstd * gam[tid + 256] + bet[tid + 256]) : 0.0f;
    __nv_bfloat16 h0, l0, h1, l1;
    bsplit(y0, h0, l0); bsplit(y1, h1, l1);
    __nv_bfloat16* e = (PASS == 0 ? g_h_ext : g_hm_ext) + (size_t)t * 1536;
    e[tid]        = h0; e[tid + 512]        = h0; e[tid + 1024]        = l0;
    e[tid + 256]  = h1; e[tid + 256 + 512]  = h1; e[tid + 256 + 1024]  = l1;
    if (PASS == 1) {
        if (tid >= dt)       outp[(size_t)t * 512 + tid]       = x0;
        if (tid + 256 >= dt) outp[(size_t)t * 512 + tid + 256] = x1;
    }
}

// fused weight conversion: all 4 weights in one launch
__global__ void wconv_all_kernel(const float* __restrict__ wqkv,
                                 const float* __restrict__ wo,
                                 const float* __restrict__ w1,
                                 const float* __restrict__ w2) {
    int i = blockIdx.x * 256 + threadIdx.x;
    const float* src; __nv_bfloat16* ext; int total, off;
    if (i < 786432)       { src = wqkv; ext = g_wqkv_ext; total = 786432;  off = i; }
    else if (i < 1048576) { src = wo;   ext = g_wo_ext;   total = 262144;  off = i - 786432; }
    else if (i < 2097152) { src = w1;   ext = g_w1_ext;   total = 1048576; off = i - 1048576; }
    else                  { src = w2;   ext = g_w2_ext;   total = 1048576; off = i - 2097152; }
    __nv_bfloat16 h, l;
    bsplit(src[off], h, l);
    ext[off] = h; ext[total + off] = l; ext[2 * total + off] = h;
}

__device__ __forceinline__ void mma16816(float* c, const uint32_t* a, const uint32_t* b) {
    asm volatile("mma.sync.aligned.m16n8k16.row.col.f32.bf16.bf16.f32 "
                 "{%0,%1,%2,%3},{%4,%5,%6,%7},{%8,%9},{%0,%1,%2,%3};"
                 : "+f"(c[0]), "+f"(c[1]), "+f"(c[2]), "+f"(c[3])
                 : "r"(a[0]), "r"(a[1]), "r"(a[2]), "r"(a[3]), "r"(b[0]), "r"(b[1]));
}

// ---------------- K-restricted QKV / O-proj GEMM (proven R9) ----------------
template<int EPI, int NC>   // EPI 0: QKV (NC=1536); EPI 1: O-proj (NC=512)
__global__ void __launch_bounds__(256, 2) tgk_kernel(const float* __restrict__ bias,
                                                     const float* __restrict__ resid) {
    const __nv_bfloat16* Aext = (EPI == 0) ? g_h_ext : g_o_ext;
    const __nv_bfloat16* Bext = (EPI == 0) ? g_wqkv_ext : g_wo_ext;

    const int tid = threadIdx.x, lane = tid & 31, wid = tid >> 5;
    const int y = blockIdx.y;
    const int b = y >> 4, seg = y & 15;
    int e, mt;
    if (seg < 2)      { e = 3; mt = seg; }
    else if (seg < 4) { e = 2; mt = seg - 2; }
    else if (seg < 8) { e = 1; mt = seg - 4; }
    else              { e = 0; mt = seg - 8; }
    const int d = 64 << e;
    const int ld = 6 + e;
    const int dm = d - 1;
    const int NS = (3 * d) >> 5;
    const int segstart = (e == 3) ? 0 : (e == 2) ? 256 : (e == 1) ? 512 : 1024;
    const int bn = blockIdx.x * 128;

    __shared__ __align__(16) unsigned char smA[2][128 * 64];
    __shared__ __align__(16) unsigned char smB[2][32 * 256];
    __shared__ int sT[128];
    if (tid < 128) sT[tid] = g_perm[b * 2048 + segstart + mt * 128 + tid];
    __syncthreads();

    const int rA0 = tid >> 2, cA = tid & 3, rA1 = rA0 + 64;
    const __nv_bfloat16* Ap0 = Aext + (size_t)(b * 2048 + sT[rA0]) * 1536 + cA * 8;
    const __nv_bfloat16* Ap1 = Aext + (size_t)(b * 2048 + sT[rA1]) * 1536 + cA * 8;
    const int oA0 = rA0 * 64 + ((cA ^ ((rA0 >> 1) & 3)) << 4);
    const int oA1 = rA1 * 64 + ((cA ^ ((rA1 >> 1) & 3)) << 4);
    const int rB0 = tid >> 4, cB = tid & 15, rB1 = rB0 + 16;
    const __nv_bfloat16* Bp0 = Bext + (size_t)rB0 * NC + bn + cB * 8;
    const __nv_bfloat16* Bp1 = Bext + (size_t)rB1 * NC + bn + cB * 8;
    const int oB0 = rB0 * 256 + ((cB ^ (rB0 & 7)) << 4);
    const int oB1 = rB1 * 256 + ((cB ^ (rB1 & 7)) << 4);

    const int wm = (wid >> 2) * 64;
    const int widn = wid & 3;

    float acc[4][4][4];
    #pragma unroll
    for (int i = 0; i < 4; i++)
        #pragma unroll
        for (int j = 0; j < 4; j++)
            #pragma unroll
            for (int k = 0; k < 4; k++) acc[i][j][k] = 0.0f;

    #define KSTAGE(buf, slab) { \
        int k0_ = (slab) * 32; int kb_ = ((k0_ >> ld) << 9) + (k0_ & dm); \
        uint32_t ba_ = (uint32_t)__cvta_generic_to_shared(smA[buf]); \
        uint32_t bb_ = (uint32_t)__cvta_generic_to_shared(smB[buf]); \
        asm volatile("cp.async.cg.shared.global [%0],[%1],16;\n" :: "r"(ba_ + oA0), "l"(Ap0 + kb_)); \
        asm volatile("cp.async.cg.shared.global [%0],[%1],16;\n" :: "r"(ba_ + oA1), "l"(Ap1 + kb_)); \
        asm volatile("cp.async.cg.shared.global [%0],[%1],16;\n" :: "r"(bb_ + oB0), "l"(Bp0 + (size_t)kb_ * NC)); \
        asm volatile("cp.async.cg.shared.global [%0],[%1],16;\n" :: "r"(bb_ + oB1), "l"(Bp1 + (size_t)kb_ * NC)); \
        asm volatile("cp.async.commit_group;\n"); }

    KSTAGE(0, 0);

    #pragma unroll 1
    for (int s = 0; s < NS; s++) {
        int cur = s & 1;
        if (s + 1 < NS) {
            KSTAGE(cur ^ 1, s + 1);
            asm volatile("cp.async.wait_group 1;\n");
        } else {
            asm volatile("cp.async.wait_group 0;\n");
        }
        __syncthreads();
        unsigned char* As = smA[cur];
        unsigned char* Bs = smB[cur];
        #pragma unroll
        for (int kk = 0; kk < 2; kk++) {
            uint32_t af[4][4], bfr[4][2];
            #pragma unroll
            for (int mi = 0; mi < 4; mi++) {
                int r = wm + mi * 16 + (lane & 7) + ((lane & 8) ? 8 : 0);
                int c = kk * 2 + ((lane & 16) ? 1 : 0);
                uint32_t sa = (uint32_t)__cvta_generic_to_shared(
                    As + r * 64 + ((c ^ ((r >> 1) & 3)) << 4));
                asm volatile("ldmatrix.sync.aligned.m8n8.x4.shared.b16 {%0,%1,%2,%3},[%4];"
                             : "=r"(af[mi][0]), "=r"(af[mi][1]), "=r"(af[mi][2]), "=r"(af[mi][3])
                             : "r"(sa));
            }
            #pragma unroll
            for (int np = 0; np < 2; np++) {
                int kr = kk * 16 + (lane & 7) + ((lane & 8) ? 8 : 0);
                int c = widn * 4 + np * 2 + ((lane & 16) ? 1 : 0);
                uint32_t sb = (uint32_t)__cvta_generic_to_shared(
                    Bs + kr * 256 + ((c ^ (kr & 7)) << 4));
                asm volatile("ldmatrix.sync.aligned.m8n8.x4.trans.shared.b16 {%0,%1,%2,%3},[%4];"
                             : "=r"(bfr[np * 2][0]), "=r"(bfr[np * 2][1]),
                               "=r"(bfr[np * 2 + 1][0]), "=r"(bfr[np * 2 + 1][1])
                             : "r"(sb));
            }
            #pragma unroll
            for (int mi = 0; mi < 4; mi++)
                #pragma unroll
                for (int ni = 0; ni < 4; ni++)
                    mma16816(acc[mi][ni], af[mi], bfr[ni]);
        }
        __syncthreads();
    }

    const int l4 = lane >> 2, l2 = (lane & 3) * 2;
    const int dt = d;
    #pragma unroll
    for (int mi = 0; mi < 4; mi++) {
        #pragma unroll
        for (int hh = 0; hh < 2; hh++) {
            int mrl = wm + mi * 16 + l4 + hh * 8;
            int tokv = sT[mrl];
            #pragma unroll
            for (int ni = 0; ni < 4; ni++) {
                int n = bn + widn * 32 + ni * 8 + l2;
                float v0 = acc[mi][ni][hh * 2 + 0];
                float v1 = acc[mi][ni][hh * 2 + 1];
                if (EPI == 0) {
                    int chunk = n >> 9, f = n & 511;
                    int head = f >> 6, dd = f & 63;
                    bool on = (f < dt);
                    float w0 = on ? v0 : 0.0f;
                    float w1 = on ? v1 : 0.0f;
                    __nv_bfloat16 hh0, ll0, hh1, ll1;
                    bsplit(w0, hh0, ll0); bsplit(w1, hh1, ll1);
                    __nv_bfloat162 hi2; hi2.x = hh0; hi2.y = hh1;
                    __nv_bfloat162 lo2; lo2.x = ll0; lo2.y = ll1;
                    size_t base = (size_t)((b * H_ + head) * N_ + tokv);
                    if (chunk == 0) {
                        __nv_bfloat16* p = g_qext + base * 192 + dd;
                        *(__nv_bfloat162*)(p)       = hi2;
                        *(__nv_bfloat162*)(p + 64)  = hi2;
                        *(__nv_bfloat162*)(p + 128) = lo2;
                    } else if (chunk == 1) {
                        __nv_bfloat16* p = g_kext + base * 192 + dd;
                        *(__nv_bfloat162*)(p)       = hi2;
                        *(__nv_bfloat162*)(p + 64)  = lo2;
                        *(__nv_bfloat162*)(p + 128) = hi2;
                    } else {
                        *(__nv_bfloat162*)(g_vh + base * 64 + dd) = hi2;
                        *(__nv_bfloat162*)(g_vl + base * 64 + dd) = lo2;
                    }
                } else {
                    size_t row = (size_t)(b * 2048 + tokv) * 512;
                    float w0 = v0 + bias[n];
                    float w1 = v1 + bias[n + 1];
                    if (n >= dt) w0 = 0.0f;
                    if (n + 1 >= dt) w1 = 0.0f;
                    const float2 xr = *(const float2*)(resid + row + n);
                    float2 o; o.x = xr.x + w0; o.y = xr.y + w1;
                    *(float2*)(g_z + row + n) = o;
                }
            }
        }
    }
    #undef KSTAGE
}

// ---------------- grouped FFN GEMMs (proven R8/R9) ----------------
template<int EPI>
__global__ void __launch_bounds__(256, 2) ggemm_kernel(const float* __restrict__ bias,
                                                       const float* __restrict__ alpha,
                                                       float* __restrict__ outp) {
    const __nv_bfloat16* Aext = (EPI == 2) ? g_hm_ext : g_hid_ext;
    const __nv_bfloat16* Bext = (EPI == 2) ? g_w1_ext : g_w2_ext;
    constexpr int NC  = (EPI == 2) ? 2048 : 512;
    constexpr int SEG = (EPI == 3) ? 2048 : 512;
    constexpr size_t AROW = 3 * SEG;
    constexpr int TN0v = (EPI == 2) ? 2 : 1;
    constexpr int TN1v = (EPI == 2) ? 4 : 1;
    constexpr int TN2v = (EPI == 2) ? 8 : 2;
    constexpr int TN3v = (EPI == 2) ? 16 : 4;
    constexpr int TS3v = (EPI == 3) ? 4 : 1;
    constexpr int TS2v = (EPI == 3) ? 2 : 1;
    constexpr int C3 = 2 * TN3v * TS3v, C2 = 2 * TN2v * TS2v, C1 = 4 * TN1v;

    const int tid = threadIdx.x, lane = tid & 31, wid = tid >> 5;
    const int b = blockIdx.y;
    int idx = blockIdx.x;
    int e, loc, TN, TS;
    if (idx < C3)                 { e = 3; loc = idx;                  TN = TN3v; TS = TS3v; }
    else if (idx < C3 + C2)       { e = 2; loc = idx - C3;             TN = TN2v; TS = TS2v; }
    else if (idx < C3 + C2 + C1)  { e = 1; loc = idx - (C3 + C2);      TN = TN1v; TS = 1; }
    else                          { e = 0; loc = idx - (C3 + C2 + C1); TN = TN0v; TS = 1; }
    const int mt = loc / (TN * TS);
    int rem = loc - mt * (TN * TS);
    const int nt = rem / TS;
    const int sp = rem - nt * TS;
    const int d = 64 << e;
    const int ld = ((EPI == 3) ? 8 : 6) + e;
    const int dm = (1 << ld) - 1;
    const int NStot = (3 << ld) >> 5;
    const int per = NStot / TS;
    const int slab0 = sp * per, slab1 = slab0 + per;
    const int segstart = (e == 0) ? 1024 : (e == 1) ? 512 : (e == 2) ? 256 : 0;

    __shared__ __align__(16) unsigned char smA[2][128 * 64];
    __shared__ __align__(16) unsigned char smB[2][32 * 256];
    __shared__ int sA[128], sT[128];
    if (tid < 128) {
        int pos = segstart + mt * 128 + tid;
        int pv = g_perm[b * 2048 + pos];
        sT[tid] = pv;
        sA[tid] = (EPI == 3) ? (b * 2048 + pos) : (b * 2048 + pv);
    }
    __syncthreads();

    const int rA0 = tid >> 2, cA = tid & 3, rA1 = rA0 + 64;
    const __nv_bfloat16* Ap0 = Aext + (size_t)sA[rA0] * AROW + cA * 8;
    const __nv_bfloat16* Ap1 = Aext + (size_t)sA[rA1] * AROW + cA * 8;
    const int oA0 = rA0 * 64 + ((cA ^ ((rA0 >> 1) & 3)) << 4);
    const int oA1 = rA1 * 64 + ((cA ^ ((rA1 >> 1) & 3)) << 4);
    const int rB0 = tid >> 4, cB = tid & 15, rB1 = rB0 + 16;
    const int bc = nt * 128 + cB * 8;
    const __nv_bfloat16* Bp0 = Bext + (size_t)rB0 * NC + bc;
    const __nv_bfloat16* Bp1 = Bext + (size_t)rB1 * NC + bc;
    const int oB0 = rB0 * 256 + ((cB ^ (rB0 & 7)) << 4);
    const int oB1 = rB1 * 256 + ((cB ^ (rB1 & 7)) << 4);

    const int wm = (wid >> 2) * 64;
    const int widn = wid & 3;

    float acc[4][4][4];
    #pragma unroll
    for (int i = 0; i < 4; i++)
        #pragma unroll
        for (int jx = 0; jx < 4; jx++)
            #pragma unroll
            for (int k = 0; k < 4; k++) acc[i][jx][k] = 0.0f;

    #define GSTAGE(buf, slab) { \
        int kk_ = (slab) * 32; int kb_ = ((kk_ >> ld) * SEG) + (kk_ & dm); \
        uint32_t ba_ = (uint32_t)__cvta_generic_to_shared(smA[buf]); \
        uint32_t bb_ = (uint32_t)__cvta_generic_to_shared(smB[buf]); \
        asm volatile("cp.async.cg.shared.global [%0],[%1],16;\n" :: "r"(ba_ + oA0), "l"(Ap0 + kb_)); \
        asm volatile("cp.async.cg.shared.global [%0],[%1],16;\n" :: "r"(ba_ + oA1), "l"(Ap1 + kb_)); \
        asm volatile("cp.async.cg.shared.global [%0],[%1],16;\n" :: "r"(bb_ + oB0), "l"(Bp0 + (size_t)kb_ * NC)); \
        asm volatile("cp.async.cg.shared.global [%0],[%1],16;\n" :: "r"(bb_ + oB1), "l"(Bp1 + (size_t)kb_ * NC)); \
        asm volatile("cp.async.commit_group;\n"); }

    GSTAGE(0, slab0);

    #pragma unroll 1
    for (int s = slab0; s < slab1; s++) {
        int cur = (s - slab0) & 1;
        if (s + 1 < slab1) {
            GSTAGE(cur ^ 1, s + 1);
            asm volatile("cp.async.wait_group 1;\n");
        } else {
            asm volatile("cp.async.wait_group 0;\n");
        }
        __syncthreads();
        unsigned char* As = smA[cur];
        unsigned char* Bs = smB[cur];
        #pragma unroll
        for (int kk = 0; kk < 2; kk++) {
            uint32_t af[4][4], bfr[4][2];
            #pragma unroll
            for (int mi = 0; mi < 4; mi++) {
                int r = wm + mi * 16 + (lane & 7) + ((lane & 8) ? 8 : 0);
                int c = kk * 2 + ((lane & 16) ? 1 : 0);
                uint32_t sa = (uint32_t)__cvta_generic_to_shared(
                    As + r * 64 + ((c ^ ((r >> 1) & 3)) << 4));
                asm volatile("ldmatrix.sync.aligned.m8n8.x4.shared.b16 {%0,%1,%2,%3},[%4];"
                             : "=r"(af[mi][0]), "=r"(af[mi][1]), "=r"(af[mi][2]), "=r"(af[mi][3])
                             : "r"(sa));
            }
            #pragma unroll
            for (int np = 0; np < 2; np++) {
                int kr = kk * 16 + (lane & 7) + ((lane & 8) ? 8 : 0);
                int c = widn * 4 + np * 2 + ((lane & 16) ? 1 : 0);
                uint32_t sb = (uint32_t)__cvta_generic_to_shared(
                    Bs + kr * 256 + ((c ^ (kr & 7)) << 4));
                asm volatile("ldmatrix.sync.aligned.m8n8.x4.trans.shared.b16 {%0,%1,%2,%3},[%4];"
                             : "=r"(bfr[np * 2][0]), "=r"(bfr[np * 2][1]),
                               "=r"(bfr[np * 2 + 1][0]), "=r"(bfr[np * 2 + 1][1])
                             : "r"(sb));
            }
            #pragma unroll
            for (int mi = 0; mi < 4; mi++)
                #pragma unroll
                for (int ni = 0; ni < 4; ni++)
                    mma16816(acc[mi][ni], af[mi], bfr[ni]);
        }
        __syncthreads();
    }

    const int l4 = lane >> 2, l2 = (lane & 3) * 2;

    if (EPI == 3 && TS > 1) {
        #pragma unroll
        for (int mi = 0; mi < 4; mi++) {
            #pragma unroll
            for (int hh = 0; hh < 2; hh++) {
                int mrl = wm + mi * 16 + l4 + hh * 8;
                int pos = segstart + mt * 128 + mrl;
                #pragma unroll
                for (int ni = 0; ni < 4; ni++) {
                    int n = nt * 128 + widn * 32 + ni * 8 + l2;
                    float2 v; v.x = acc[mi][ni][hh * 2]; v.y = acc[mi][ni][hh * 2 + 1];
                    *(float2*)&g_fpart[sp][((b << 9) + pos) * 512 + n] = v;
                }
            }
        }
        return;
    }

    float aval = 0.0f;
    if (EPI == 3) aval = alpha[0];

    #pragma unroll
    for (int mi = 0; mi < 4; mi++) {
        #pragma unroll
        for (int hh = 0; hh < 2; hh++) {
            int mrl = wm + mi * 16 + l4 + hh * 8;
            int tok = sT[mrl];
            #pragma unroll
            for (int ni = 0; ni < 4; ni++) {
                int n = nt * 128 + widn * 32 + ni * 8 + l2;
                float v0 = acc[mi][ni][hh * 2 + 0];
                float v1 = acc[mi][ni][hh * 2 + 1];
                if (EPI == 2) {
                    if (n < 4 * d) {
                        int pos = segstart + mt * 128 + mrl;
                        size_t row = (size_t)(b * 2048 + pos) * 6144;
                        float w = v0 + bias[n];
                        float c1 = 0.7978845608028654f * (w + 0.044715f * w * w * w);
                        float h0 = 0.5f * w * (1.0f + tanhf(c1));
                        w = v1 + bias[n + 1];
                        c1 = 0.7978845608028654f * (w + 0.044715f * w * w * w);
                        float h1 = 0.5f * w * (1.0f + tanhf(c1));
                        __nv_bfloat16 a0, b0, a1, b1;
                        bsplit(h0, a0, b0); bsplit(h1, a1, b1);
                        __nv_bfloat162 hi; hi.x = a0; hi.y = a1;
                        __nv_bfloat162 lo; lo.x = b0; lo.y = b1;
                        *(__nv_bfloat162*)(g_hid_ext + row + n)        = hi;
                        *(__nv_bfloat162*)(g_hid_ext + row + n + 2048) = hi;
                        *(__nv_bfloat162*)(g_hid_ext + row + n + 4096) = lo;
                    }
                } else {
                    if (n < d) {
                        size_t row = (size_t)(b * 2048 + tok) * 512;
                        float gm = aval * g_rp[b * 2048 + tok] + 1.0f;
                        float w0 = v0 + bias[n];
                        float w1 = v1 + bias[n + 1];
                        const float2 zz = *(const float2*)(g_z + row + n);
                        float2 o; o.x = zz.x + gm * w0; o.y = zz.y + gm * w1;
                        *(float2*)(outp + row + n) = o;
                    }
                }
            }
        }
    }
    #undef GSTAGE
}

__global__ void reduce3_kernel(const float* __restrict__ b2f,
                               const float* __restrict__ alpha,
                               float* __restrict__ outp) {
    int rowid = blockIdx.x;
    int b = rowid >> 9, pos = rowid & 511;
    int ns = (pos < 256) ? 4 : 2;
    int d = (pos < 256) ? 512 : 256;
    int tok = g_perm[b * 2048 + pos];
    float gm = alpha[0] * g_rp[b * 2048 + tok] + 1.0f;
    size_t row = (size_t)(b * 2048 + tok) * 512;
    int base = ((b << 9) + pos) * 512;
    for (int n = threadIdx.x; n < d; n += 256) {
        float s = g_fpart[0][base + n] + g_fpart[1][base + n];
        if (ns == 4) s += g_fpart[2][base + n] + g_fpart[3][base + n];
        s += b2f[n];
        outp[row + n] = g_z[row + n] + gm * s;
    }
}

// ---------------- tensor-core flash attention, single buffer + split K/V waits ----------------
// smem: Q 25600 + K 25600 + Vh 9216 + Vl 9216 = 69632 B -> 3 CTAs/SM (one wave)
// K committed as its own group; V as another. S-phase waits only K; V load overlaps S+softmax.
__global__ void __launch_bounds__(128, 3) fattn_kernel() {
    const int b = blockIdx.y;
    const int slot = blockIdx.x;
    const int h = c_head[slot];
    const int ch = c_chunk[slot];
    extern __shared__ __align__(16) unsigned char sm[];
    unsigned char* Qs  = sm;
    unsigned char* Ks  = sm + 25600;
    unsigned char* Vhs = sm + 2 * 25600;
    unsigned char* Vls = Vhs + 9216;
    __shared__ int tok[64];
    const int tid = threadIdx.x, lane = tid & 31, wid = tid >> 5;

    if (tid < 64) tok[tid] = g_perm[b * N_ + ch * 64 + tid];
    __syncthreads();
    const size_t bh = (size_t)(b * H_ + h) * N_;

    // Q load (its own group; folded into first iteration's K wait)
    for (int i = tid; i < 64 * 24; i += 128) {
        int r = i / 24, c = i % 24;
        const __nv_bfloat16* g = g_qext + (bh + tok[r]) * 192 + c * 8;
        uint32_t s = (uint32_t)__cvta_generic_to_shared(Qs + r * 400 + c * 16);
        asm volatile("cp.async.cg.shared.global [%0],[%1],16;\n" :: "r"(s), "l"(g));
    }
    asm volatile("cp.async.commit_group;\n");

    float accO[8][4];
    #pragma unroll
    for (int i = 0; i < 8; i++)
        #pragma unroll
        for (int j = 0; j < 4; j++) accO[i][j] = 0.0f;
    float m0 = -3.0e38f, m1 = -3.0e38f, l0 = 0.0f, l1 = 0.0f;

    const int qrow = wid * 16 + (lane & 15);
    const int krow7 = (lane & 7) + ((lane & 16) ? 8 : 0);
    const int kcsel = ((lane & 8) ? 1 : 0);
    const int vrow7 = (lane & 7) + ((lane & 8) ? 8 : 0);
    const int vcsel = ((lane & 16) ? 1 : 0);

    #pragma unroll 1
    for (int k0 = 0; k0 < N_; k0 += 64) {
        // K tile -> group A
        for (int i = tid; i < 64 * 24; i += 128) {
            int r = i / 24, c = i % 24;
            const __nv_bfloat16* g = g_kext + (bh + k0 + r) * 192 + c * 8;
            uint32_t s = (uint32_t)__cvta_generic_to_shared(Ks + r * 400 + c * 16);
            asm volatile("cp.async.cg.shared.global [%0],[%1],16;\n" :: "r"(s), "l"(g));
        }
        asm volatile("cp.async.commit_group;\n");
        // V tiles -> group B
        for (int i = tid; i < 64 * 8; i += 128) {
            int r = i / 8, c = i % 8;
            const __nv_bfloat16* gh = g_vh + (bh + k0 + r) * 64 + c * 8;
            const __nv_bfloat16* gl = g_vl + (bh + k0 + r) * 64 + c * 8;
            uint32_t sh = (uint32_t)__cvta_generic_to_shared(Vhs + r * 144 + c * 16);
            uint32_t sl = (uint32_t)__cvta_generic_to_shared(Vls + r * 144 + c * 16);
            asm volatile("cp.async.cg.shared.global [%0],[%1],16;\n" :: "r"(sh), "l"(gh));
            asm volatile("cp.async.cg.shared.global [%0],[%1],16;\n" :: "r"(sl), "l"(gl));
        }
        asm volatile("cp.async.commit_group;\n");

        // wait K (V may still be in flight)
        asm volatile("cp.async.wait_group 1;\n");
        __syncthreads();

        float S[8][4];
        #pragma unroll
        for (int i = 0; i < 8; i++)
            #pragma unroll
            for (int j = 0; j < 4; j++) S[i][j] = 0.0f;

        #pragma unroll
        for (int ks = 0; ks < 12; ks++) {
            uint32_t qf[4];
            uint32_t sa = (uint32_t)__cvta_generic_to_shared(
                Qs + qrow * 400 + (ks * 2 + (lane >> 4)) * 16);
            asm volatile("ldmatrix.sync.aligned.m8n8.x4.shared.b16 {%0,%1,%2,%3},[%4];"
                         : "=r"(qf[0]), "=r"(qf[1]), "=r"(qf[2]), "=r"(qf[3]) : "r"(sa));
            #pragma unroll
            for (int p = 0; p < 4; p++) {
                uint32_t kf[4];
                uint32_t sb = (uint32_t)__cvta_generic_to_shared(
                    Ks + (p * 16 + krow7) * 400 + (ks * 2 + kcsel) * 16);
                asm volatile("ldmatrix.sync.aligned.m8n8.x4.shared.b16 {%0,%1,%2,%3},[%4];"
                             : "=r"(kf[0]), "=r"(kf[1]), "=r"(kf[2]), "=r"(kf[3]) : "r"(sb));
                mma16816(S[2 * p],     qf, kf);
                mma16816(S[2 * p + 1], qf, kf + 2);
            }
        }

        float mx0 = -3.0e38f, mx1 = -3.0e38f;
        #pragma unroll
        for (int ni = 0; ni < 8; ni++) {
            S[ni][0] *= 0.125f; S[ni][1] *= 0.125f; S[ni][2] *= 0.125f; S[ni][3] *= 0.125f;
            mx0 = fmaxf(mx0, fmaxf(S[ni][0], S[ni][1]));
            mx1 = fmaxf(mx1, fmaxf(S[ni][2], S[ni][3]));
        }
        mx0 = fmaxf(mx0, __shfl_xor_sync(0xffffffffu, mx0, 1));
        mx0 = fmaxf(mx0, __shfl_xor_sync(0xffffffffu, mx0, 2));
        mx1 = fmaxf(mx1, __shfl_xor_sync(0xffffffffu, mx1, 1));
        mx1 = fmaxf(mx1, __shfl_xor_sync(0xffffffffu, mx1, 2));
        float mn0 = fmaxf(m0, mx0), mn1 = fmaxf(m1, mx1);
        float cr0 = __expf(m0 - mn0), cr1 = __expf(m1 - mn1);
        float s0 = 0.0f, s1 = 0.0f;
        uint32_t pha[8], phb[8], pla[8], plb[8];
        #pragma unroll
        for (int ni = 0; ni < 8; ni++) {
            float p00 = __expf(S[ni][0] - mn0), p01 = __expf(S[ni][1] - mn0);
            float p10 = __expf(S[ni][2] - mn1), p11 = __expf(S[ni][3] - mn1);
            s0 += p00 + p01; s1 += p10 + p11;
            __nv_bfloat16 h00, l00, h01, l01, h10, l10, h11, l11;
            bsplit(p00, h00, l00); bsplit(p01, h01, l01);
            bsplit(p10, h10, l10); bsplit(p11, h11, l11);
            pha[ni] = packb(h00, h01); phb[ni] = packb(h10, h11);
            pla[ni] = packb(l00, l01); plb[ni] = packb(l10, l11);
        }
        s0 += __shfl_xor_sync(0xffffffffu, s0, 1);
        s0 += __shfl_xor_sync(0xffffffffu, s0, 2);
        s1 += __shfl_xor_sync(0xffffffffu, s1, 1);
        s1 += __shfl_xor_sync(0xffffffffu, s1, 2);
        l0 = l0 * cr0 + s0; l1 = l1 * cr1 + s1;
        m0 = mn0; m1 = mn1;
        #pragma unroll
        for (int ni = 0; ni < 8; ni++) {
            accO[ni][0] *= cr0; accO[ni][1] *= cr0;
            accO[ni][2] *= cr1; accO[ni][3] *= cr1;
        }

        // wait V (loaded during S + softmax)
        asm volatile("cp.async.wait_group 0;\n");
        __syncthreads();

        #pragma unroll
        for (int kt = 0; kt < 4; kt++) {
            uint32_t pa[4] = {pha[2 * kt], phb[2 * kt], pha[2 * kt + 1], phb[2 * kt + 1]};
            uint32_t la[4] = {pla[2 * kt], plb[2 * kt], pla[2 * kt + 1], plb[2 * kt + 1]};
            #pragma unroll
            for (int p = 0; p < 4; p++) {
                uint32_t vh[4], vl[4];
                uint32_t svh = (uint32_t)__cvta_generic_to_shared(
                    Vhs + (kt * 16 + vrow7) * 144 + (p * 2 + vcsel) * 16);
                uint32_t svl = (uint32_t)__cvta_generic_to_shared(
                    Vls + (kt * 16 + vrow7) * 144 + (p * 2 + vcsel) * 16);
                asm volatile("ldmatrix.sync.aligned.m8n8.x4.trans.shared.b16 {%0,%1,%2,%3},[%4];"
                             : "=r"(vh[0]), "=r"(vh[1]), "=r"(vh[2]), "=r"(vh[3]) : "r"(svh));
                asm volatile("ldmatrix.sync.aligned.m8n8.x4.trans.shared.b16 {%0,%1,%2,%3},[%4];"
                             : "=r"(vl[0]), "=r"(vl[1]), "=r"(vl[2]), "=r"(vl[3]) : "r"(svl));
                mma16816(accO[2 * p],     pa, vh);
                mma16816(accO[2 * p + 1], pa, vh + 2);
                mma16816(accO[2 * p],     pa, vl);
                mma16816(accO[2 * p + 1], pa, vl + 2);
                mma16816(accO[2 * p],     la, vh);
                mma16816(accO[2 * p + 1], la, vh + 2);
            }
        }
        __syncthreads();
    }

    float inv0 = 1.0f / l0, inv1 = 1.0f / l1;
    const int ilo = wid * 16 + (lane >> 2);
    const int ihi = ilo + 8;
    const size_t rlo = (size_t)(b * N_ + tok[ilo]) * 1536 + h * 64 + (lane & 3) * 2;
    const size_t rhi = (size_t)(b * N_ + tok[ihi]) * 1536 + h * 64 + (lane & 3) * 2;
    #pragma unroll
    for (int ni = 0; ni < 8; ni++) {
        float o0 = accO[ni][0] * inv0, o1 = accO[ni][1] * inv0;
        float o2 = accO[ni][2] * inv1, o3 = accO[ni][3] * inv1;
        __nv_bfloat16 h0, q0, h1, q1, h2, q2, h3, q3;
        bsplit(o0, h0, q0); bsplit(o1, h1, q1);
        bsplit(o2, h2, q2); bsplit(o3, h3, q3);
        __nv_bfloat162 hiA; hiA.x = h0; hiA.y = h1;
        __nv_bfloat162 loA; loA.x = q0; loA.y = q1;
        __nv_bfloat162 hiB; hiB.x = h2; hiB.y = h3;
        __nv_bfloat162 loB; loB.x = q2; loB.y = q3;
        *(__nv_bfloat162*)(g_o_ext + rlo + ni * 8)        = hiA;
        *(__nv_bfloat162*)(g_o_ext + rlo + ni * 8 + 512)  = hiA;
        *(__nv_bfloat162*)(g_o_ext + rlo + ni * 8 + 1024) = loA;
        *(__nv_bfloat162*)(g_o_ext + rhi + ni * 8)        = hiB;
        *(__nv_bfloat162*)(g_o_ext + rhi + ni * 8 + 512)  = hiB;
        *(__nv_bfloat162*)(g_o_ext + rhi + ni * 8 + 1024) = loB;
    }
}

__global__ void extras_kernel(float* __restrict__ outp, int write_rp) {
    int i = blockIdx.x * 256 + threadIdx.x;
    if (i < MT) {
        outp[MT * D_ + i] = (float)g_assigned[i];
        if (write_rp) outp[MT * D_ + MT + i] = g_rp[i];
    }
}

extern "C" void kernel_launch(void* const* d_in, const int* in_sizes, int n_in,
                              void* d_out, int out_size) {
    const float* x     = (const float*)d_in[0];
    const float* r_w   = (const float*)d_in[1];
    const float* r_b   = (const float*)d_in[2];
    const float* g1    = (const float*)d_in[3];
    const float* b1    = (const float*)d_in[4];
    const float* g2    = (const float*)d_in[5];
    const float* b2    = (const float*)d_in[6];
    const float* w_qkv = (const float*)d_in[7];
    const float* w_o   = (const float*)d_in[8];
    const float* b_o   = (const float*)d_in[9];
    const float* w1    = (const float*)d_in[10];
    const float* b1f   = (const float*)d_in[11];
    const float* w2    = (const float*)d_in[12];
    const float* b2f   = (const float*)d_in[13];
    const float* alpha = (const float*)d_in[14];
    float* out = (float*)d_out;

    static const int FATTN_SMEM = 2 * 25600 + 2 * 9216;   // 69632
    cudaFuncSetAttribute(fattn_kernel, cudaFuncAttributeMaxDynamicSharedMemorySize, FATTN_SMEM);

    router_kernel<<<MT / 8, 256>>>(x, r_w, r_b);
    assign_kernel<<<B_, 1024>>>();
    wconv_all_kernel<<<3145728 / 256, 256>>>(w_qkv, w_o, w1, w2);

    ln_kernel<0><<<MT, 256>>>(x, g1, b1, nullptr);
    tgk_kernel<0, 1536><<<dim3(12, 64), 256>>>(nullptr, nullptr);
    fattn_kernel<<<dim3(80, B_), 128, FATTN_SMEM>>>();
    tgk_kernel<1, 512><<<dim3(4, 64), 256>>>(b_o, x);
    ln_kernel<1><<<MT, 256>>>(x, g2, b2, out);
    ggemm_kernel<2><<<dim3(80, B_), 256>>>(b1f, nullptr, nullptr);
    ggemm_kernel<3><<<dim3(52, B_), 256>>>(b2f, alpha, out);
    reduce3_kernel<<<B_ * 512, 256>>>(b2f, alpha, out);

    if (out_size >= MT * D_ + MT) {
        int write_rp = (out_size >= MT * D_ + 2 * MT) ? 1 : 0;
        extras_kernel<<<(MT + 255) / 256, 256>>>(out, write_rp);
    }
}

// round 12
// speedup vs baseline: 1.1753x; 1.1472x over previous
#include <cuda_runtime.h>
#include <cuda_bf16.h>
#include <cstdint>
#include <math.h>

#define B_  4
#define N_  2048
#define D_  512
#define H_  8
#define E_  4
#define MT  (B_*N_)

__device__ float g_probs[MT*E_];
__device__ int   g_dtok[MT];
__device__ int   g_assigned[MT];
__device__ int   g_perm[MT];
__device__ float g_rp[MT];
__device__ float g_z [MT*D_];
__device__ float g_fpart[4][B_*512*512];
__device__ __nv_bfloat16 g_h_ext  [MT*1536];
__device__ __nv_bfloat16 g_o_ext  [MT*1536];
__device__ __nv_bfloat16 g_hm_ext [MT*1536];
__device__ __nv_bfloat16 g_hid_ext[(size_t)MT*6144];   // permuted rows
__device__ __nv_bfloat16 g_qext[(size_t)B_*H_*N_*128]; // [Qh|Ql] along d
__device__ __nv_bfloat16 g_kext[(size_t)B_*H_*N_*128]; // [Kh|Kh] along d
__device__ __nv_bfloat16 g_vh [(size_t)B_*H_*N_*64];
__device__ __nv_bfloat16 g_vl [(size_t)B_*H_*N_*64];
__device__ __nv_bfloat16 g_wqkv_ext[1536*1536];
__device__ __nv_bfloat16 g_wo_ext  [1536*512];
__device__ __nv_bfloat16 g_w1_ext  [1536*2048];
__device__ __nv_bfloat16 g_w2_ext  [6144*512];

__constant__ int c_head[80] = {
    0,0,0,0,0,0,0,0,0,0,0,0,0,0,0,0,0,0,0,0,0,0,0,0,0,0,0,0,0,0,0,0,
    1,1,1,1,1,1,1,1,1,1,1,1,1,1,1,1,
    2,2,2,2,2,2,2,2, 3,3,3,3,3,3,3,3,
    4,4,4,4, 5,5,5,5, 6,6,6,6, 7,7,7,7};
__constant__ int c_chunk[80] = {
    0,1,2,3,4,5,6,7,8,9,10,11,12,13,14,15,16,17,18,19,20,21,22,23,24,25,26,27,28,29,30,31,
    0,1,2,3,4,5,6,7,8,9,10,11,12,13,14,15,
    0,1,2,3,4,5,6,7, 0,1,2,3,4,5,6,7,
    0,1,2,3, 0,1,2,3, 0,1,2,3, 0,1,2,3};

__device__ __forceinline__ void bsplit(float v, __nv_bfloat16& h, __nv_bfloat16& l) {
    h = __float2bfloat16(v);
    l = __float2bfloat16(v - __bfloat162float(h));
}
__device__ __forceinline__ uint32_t packb(__nv_bfloat16 a, __nv_bfloat16 b) {
    __nv_bfloat162 t; t.x = a; t.y = b; return *(uint32_t*)&t;
}

__global__ void router_kernel(const float* __restrict__ x,
                              const float* __restrict__ rw,
                              const float* __restrict__ rb) {
    int warp = threadIdx.x >> 5, lane = threadIdx.x & 31;
    int t = blockIdx.x * 8 + warp;
    const float* xr = x + t * D_;
    double a0 = 0, a1 = 0, a2 = 0, a3 = 0;
    for (int j = lane; j < D_; j += 32) {
        double xv = (double)xr[j];
        const float* w = rw + j * E_;
        a0 += xv * (double)w[0]; a1 += xv * (double)w[1];
        a2 += xv * (double)w[2]; a3 += xv * (double)w[3];
    }
    #pragma unroll
    for (int o = 16; o > 0; o >>= 1) {
        a0 += __shfl_down_sync(0xffffffffu, a0, o);
        a1 += __shfl_down_sync(0xffffffffu, a1, o);
        a2 += __shfl_down_sync(0xffffffffu, a2, o);
        a3 += __shfl_down_sync(0xffffffffu, a3, o);
    }
    if (lane == 0) {
        double l0 = a0 + (double)rb[0], l1 = a1 + (double)rb[1];
        double l2 = a2 + (double)rb[2], l3 = a3 + (double)rb[3];
        double mx = fmax(fmax(l0, l1), fmax(l2, l3));
        double e0 = exp(l0 - mx), e1 = exp(l1 - mx), e2 = exp(l2 - mx), e3 = exp(l3 - mx);
        double s = e0 + e1 + e2 + e3;
        float* p = g_probs + t * 4;
        p[0] = (float)(e0 / s); p[1] = (float)(e1 / s);
        p[2] = (float)(e2 / s); p[3] = (float)(e3 / s);
    }
}

__device__ __forceinline__ unsigned int f2ord(float f) {
    unsigned int u = __float_as_uint(f);
    return (u & 0x80000000u) ? ~u : (u | 0x80000000u);
}

__global__ __launch_bounds__(1024) void assign_kernel() {
    const int b = blockIdx.x, tid = threadIdx.x;
    __shared__ unsigned long long key[N_];
    __shared__ int sas[N_];
    __shared__ int cnt[4];
    sas[tid] = -1; sas[tid + 1024] = -1;
    if (tid < 4) cnt[tid] = 0;
    __syncthreads();
    const int capByE[4] = {1024, 512, 256, 256};
    for (int p = 0; p < 3; p++) {
        const int e = 3 - p, cap = capByE[e];
        #pragma unroll
        for (int ii = 0; ii < 2; ii++) {
            int i = tid + ii * 1024;
            float pr = (sas[i] < 0) ? g_probs[(b * N_ + i) * E_ + e] : -1.0f;
            key[i] = ((unsigned long long)f2ord(pr) << 32) | (unsigned int)(0xFFFFFFFFu - (unsigned)i);
        }
        __syncthreads();
        for (int k = 2; k <= N_; k <<= 1) {
            for (int j = k >> 1; j > 0; j >>= 1) {
                #pragma unroll
                for (int ii = 0; ii < 2; ii++) {
                    int i = tid + ii * 1024, ixj = i ^ j;
                    if (ixj > i) {
                        unsigned long long a = key[i], c = key[ixj];
                        bool sw = ((i & k) == 0) ? (a < c) : (a > c);
                        if (sw) { key[i] = c; key[ixj] = a; }
                    }
                }
                __syncthreads();
            }
        }
        #pragma unroll
        for (int ii = 0; ii < 2; ii++) {
            int pos = tid + ii * 1024;
            if (pos < cap) {
                unsigned long long kk = key[pos];
                if ((unsigned int)(kk >> 32) >= 0x80000000u)
                    sas[(int)(0xFFFFFFFFu - (unsigned int)(kk & 0xFFFFFFFFu))] = e;
            }
        }
        __syncthreads();
    }
    const int startE[4] = {1024, 512, 256, 0};
    #pragma unroll
    for (int ii = 0; ii < 2; ii++) {
        int i = tid + ii * 1024;
        int a = sas[i]; if (a < 0) a = 0;
        int gi = b * N_ + i;
        g_assigned[gi] = a;
        g_dtok[gi] = 64 << a;
        g_rp[gi] = g_probs[gi * E_ + a];
        int pos = startE[a] + atomicAdd(&cnt[a], 1);
        g_perm[b * N_ + pos] = i;
    }
}

// ln: warp-per-token, register-resident, shuffle reductions (no smem/sync)
// PASS 1 also writes out's masked cols (= z)
template<int PASS>
__global__ __launch_bounds__(256) void ln_kernel(const float* __restrict__ xin,
                                                 const float* __restrict__ gam,
                                                 const float* __restrict__ bet,
                                                 float* __restrict__ outp) {
    const int warp = threadIdx.x >> 5, lane = threadIdx.x & 31;
    const int t = blockIdx.x * 8 + warp;
    const float* r = (PASS == 0 ? xin : g_z) + (size_t)t * 512;
    float2 v[8];
    float s = 0.0f;
    #pragma unroll
    for (int i = 0; i < 8; i++) {
        v[i] = *(const float2*)(r + lane * 2 + 64 * i);
        s += v[i].x + v[i].y;
    }
    #pragma unroll
    for (int o = 16; o > 0; o >>= 1) s += __shfl_xor_sync(0xffffffffu, s, o);
    float mu = s * (1.0f / 512.0f);
    float q = 0.0f;
    #pragma unroll
    for (int i = 0; i < 8; i++) {
        float d0 = v[i].x - mu, d1 = v[i].y - mu;
        q += d0 * d0 + d1 * d1;
    }
    #pragma unroll
    for (int o = 16; o > 0; o >>= 1) q += __shfl_xor_sync(0xffffffffu, q, o);
    float rstd = rsqrtf(q * (1.0f / 512.0f) + 1e-5f);
    int dt = g_dtok[t];
    __nv_bfloat16* e = (PASS == 0 ? g_h_ext : g_hm_ext) + (size_t)t * 1536;
    #pragma unroll
    for (int i = 0; i < 8; i++) {
        int j = lane * 2 + 64 * i;
        bool on = (j < dt);   // dt multiple of 64, j even -> pairwise uniform
        float y0 = on ? ((v[i].x - mu) * rstd * gam[j]     + bet[j])     : 0.0f;
        float y1 = on ? ((v[i].y - mu) * rstd * gam[j + 1] + bet[j + 1]) : 0.0f;
        __nv_bfloat16 h0, l0, h1, l1;
        bsplit(y0, h0, l0); bsplit(y1, h1, l1);
        __nv_bfloat162 hi; hi.x = h0; hi.y = h1;
        __nv_bfloat162 lo; lo.x = l0; lo.y = l1;
        *(__nv_bfloat162*)(e + j)        = hi;
        *(__nv_bfloat162*)(e + j + 512)  = hi;
        *(__nv_bfloat162*)(e + j + 1024) = lo;
        if (PASS == 1 && !on) *(float2*)(outp + (size_t)t * 512 + j) = v[i];
    }
}

// fused weight conversion: all 4 weights in one launch
__global__ void wconv_all_kernel(const float* __restrict__ wqkv,
                                 const float* __restrict__ wo,
                                 const float* __restrict__ w1,
                                 const float* __restrict__ w2) {
    int i = blockIdx.x * 256 + threadIdx.x;
    const float* src; __nv_bfloat16* ext; int total, off;
    if (i < 786432)       { src = wqkv; ext = g_wqkv_ext; total = 786432;  off = i; }
    else if (i < 1048576) { src = wo;   ext = g_wo_ext;   total = 262144;  off = i - 786432; }
    else if (i < 2097152) { src = w1;   ext = g_w1_ext;   total = 1048576; off = i - 1048576; }
    else                  { src = w2;   ext = g_w2_ext;   total = 1048576; off = i - 2097152; }
    __nv_bfloat16 h, l;
    bsplit(src[off], h, l);
    ext[off] = h; ext[total + off] = l; ext[2 * total + off] = h;
}

__device__ __forceinline__ void mma16816(float* c, const uint32_t* a, const uint32_t* b) {
    asm volatile("mma.sync.aligned.m16n8k16.row.col.f32.bf16.bf16.f32 "
                 "{%0,%1,%2,%3},{%4,%5,%6,%7},{%8,%9},{%0,%1,%2,%3};"
                 : "+f"(c[0]), "+f"(c[1]), "+f"(c[2]), "+f"(c[3])
                 : "r"(a[0]), "r"(a[1]), "r"(a[2]), "r"(a[3]), "r"(b[0]), "r"(b[1]));
}

// ---------------- K-restricted QKV / O-proj GEMM ----------------
template<int EPI, int NC>   // EPI 0: QKV (NC=1536); EPI 1: O-proj (NC=512)
__global__ void __launch_bounds__(256, 2) tgk_kernel(const float* __restrict__ bias,
                                                     const float* __restrict__ resid) {
    const __nv_bfloat16* Aext = (EPI == 0) ? g_h_ext : g_o_ext;
    const __nv_bfloat16* Bext = (EPI == 0) ? g_wqkv_ext : g_wo_ext;

    const int tid = threadIdx.x, lane = tid & 31, wid = tid >> 5;
    const int y = blockIdx.y;
    const int b = y >> 4, seg = y & 15;
    int e, mt;
    if (seg < 2)      { e = 3; mt = seg; }
    else if (seg < 4) { e = 2; mt = seg - 2; }
    else if (seg < 8) { e = 1; mt = seg - 4; }
    else              { e = 0; mt = seg - 8; }
    const int d = 64 << e;
    const int ld = 6 + e;
    const int dm = d - 1;
    const int NS = (3 * d) >> 5;
    const int segstart = (e == 3) ? 0 : (e == 2) ? 256 : (e == 1) ? 512 : 1024;
    const int bn = blockIdx.x * 128;

    __shared__ __align__(16) unsigned char smA[2][128 * 64];
    __shared__ __align__(16) unsigned char smB[2][32 * 256];
    __shared__ int sT[128];
    if (tid < 128) sT[tid] = g_perm[b * 2048 + segstart + mt * 128 + tid];
    __syncthreads();

    const int rA0 = tid >> 2, cA = tid & 3, rA1 = rA0 + 64;
    const __nv_bfloat16* Ap0 = Aext + (size_t)(b * 2048 + sT[rA0]) * 1536 + cA * 8;
    const __nv_bfloat16* Ap1 = Aext + (size_t)(b * 2048 + sT[rA1]) * 1536 + cA * 8;
    const int oA0 = rA0 * 64 + ((cA ^ ((rA0 >> 1) & 3)) << 4);
    const int oA1 = rA1 * 64 + ((cA ^ ((rA1 >> 1) & 3)) << 4);
    const int rB0 = tid >> 4, cB = tid & 15, rB1 = rB0 + 16;
    const __nv_bfloat16* Bp0 = Bext + (size_t)rB0 * NC + bn + cB * 8;
    const __nv_bfloat16* Bp1 = Bext + (size_t)rB1 * NC + bn + cB * 8;
    const int oB0 = rB0 * 256 + ((cB ^ (rB0 & 7)) << 4);
    const int oB1 = rB1 * 256 + ((cB ^ (rB1 & 7)) << 4);

    const int wm = (wid >> 2) * 64;
    const int widn = wid & 3;

    float acc[4][4][4];
    #pragma unroll
    for (int i = 0; i < 4; i++)
        #pragma unroll
        for (int j = 0; j < 4; j++)
            #pragma unroll
            for (int k = 0; k < 4; k++) acc[i][j][k] = 0.0f;

    #define KSTAGE(buf, slab) { \
        int k0_ = (slab) * 32; int kb_ = ((k0_ >> ld) << 9) + (k0_ & dm); \
        uint32_t ba_ = (uint32_t)__cvta_generic_to_shared(smA[buf]); \
        uint32_t bb_ = (uint32_t)__cvta_generic_to_shared(smB[buf]); \
        asm volatile("cp.async.cg.shared.global [%0],[%1],16;\n" :: "r"(ba_ + oA0), "l"(Ap0 + kb_)); \
        asm volatile("cp.async.cg.shared.global [%0],[%1],16;\n" :: "r"(ba_ + oA1), "l"(Ap1 + kb_)); \
        asm volatile("cp.async.cg.shared.global [%0],[%1],16;\n" :: "r"(bb_ + oB0), "l"(Bp0 + (size_t)kb_ * NC)); \
        asm volatile("cp.async.cg.shared.global [%0],[%1],16;\n" :: "r"(bb_ + oB1), "l"(Bp1 + (size_t)kb_ * NC)); \
        asm volatile("cp.async.commit_group;\n"); }

    KSTAGE(0, 0);

    #pragma unroll 1
    for (int s = 0; s < NS; s++) {
        int cur = s & 1;
        if (s + 1 < NS) {
            KSTAGE(cur ^ 1, s + 1);
            asm volatile("cp.async.wait_group 1;\n");
        } else {
            asm volatile("cp.async.wait_group 0;\n");
        }
        __syncthreads();
        unsigned char* As = smA[cur];
        unsigned char* Bs = smB[cur];
        #pragma unroll
        for (int kk = 0; kk < 2; kk++) {
            uint32_t af[4][4], bfr[4][2];
            #pragma unroll
            for (int mi = 0; mi < 4; mi++) {
                int r = wm + mi * 16 + (lane & 7) + ((lane & 8) ? 8 : 0);
                int c = kk * 2 + ((lane & 16) ? 1 : 0);
                uint32_t sa = (uint32_t)__cvta_generic_to_shared(
                    As + r * 64 + ((c ^ ((r >> 1) & 3)) << 4));
                asm volatile("ldmatrix.sync.aligned.m8n8.x4.shared.b16 {%0,%1,%2,%3},[%4];"
                             : "=r"(af[mi][0]), "=r"(af[mi][1]), "=r"(af[mi][2]), "=r"(af[mi][3])
                             : "r"(sa));
            }
            #pragma unroll
            for (int np = 0; np < 2; np++) {
                int kr = kk * 16 + (lane & 7) + ((lane & 8) ? 8 : 0);
                int c = widn * 4 + np * 2 + ((lane & 16) ? 1 : 0);
                uint32_t sb = (uint32_t)__cvta_generic_to_shared(
                    Bs + kr * 256 + ((c ^ (kr & 7)) << 4));
                asm volatile("ldmatrix.sync.aligned.m8n8.x4.trans.shared.b16 {%0,%1,%2,%3},[%4];"
                             : "=r"(bfr[np * 2][0]), "=r"(bfr[np * 2][1]),
                               "=r"(bfr[np * 2 + 1][0]), "=r"(bfr[np * 2 + 1][1])
                             : "r"(sb));
            }
            #pragma unroll
            for (int mi = 0; mi < 4; mi++)
                #pragma unroll
                for (int ni = 0; ni < 4; ni++)
                    mma16816(acc[mi][ni], af[mi], bfr[ni]);
        }
        __syncthreads();
    }

    const int l4 = lane >> 2, l2 = (lane & 3) * 2;
    const int dt = d;
    #pragma unroll
    for (int mi = 0; mi < 4; mi++) {
        #pragma unroll
        for (int hh = 0; hh < 2; hh++) {
            int mrl = wm + mi * 16 + l4 + hh * 8;
            int tokv = sT[mrl];
            #pragma unroll
            for (int ni = 0; ni < 4; ni++) {
                int n = bn + widn * 32 + ni * 8 + l2;
                float v0 = acc[mi][ni][hh * 2 + 0];
                float v1 = acc[mi][ni][hh * 2 + 1];
                if (EPI == 0) {
                    int chunk = n >> 9, f = n & 511;
                    int head = f >> 6, dd = f & 63;
                    bool on = (f < dt);
                    float w0 = on ? v0 : 0.0f;
                    float w1 = on ? v1 : 0.0f;
                    __nv_bfloat16 hh0, ll0, hh1, ll1;
                    bsplit(w0, hh0, ll0); bsplit(w1, hh1, ll1);
                    __nv_bfloat162 hi2; hi2.x = hh0; hi2.y = hh1;
                    __nv_bfloat162 lo2; lo2.x = ll0; lo2.y = ll1;
                    size_t base = (size_t)((b * H_ + head) * N_ + tokv);
                    if (chunk == 0) {        // Q: [hi|lo]
                        __nv_bfloat16* p = g_qext + base * 128 + dd;
                        *(__nv_bfloat162*)(p)      = hi2;
                        *(__nv_bfloat162*)(p + 64) = lo2;
                    } else if (chunk == 1) { // K: [hi|hi]
                        __nv_bfloat16* p = g_kext + base * 128 + dd;
                        *(__nv_bfloat162*)(p)      = hi2;
                        *(__nv_bfloat162*)(p + 64) = hi2;
                    } else {
                        *(__nv_bfloat162*)(g_vh + base * 64 + dd) = hi2;
                        *(__nv_bfloat162*)(g_vl + base * 64 + dd) = lo2;
                    }
                } else {
                    size_t row = (size_t)(b * 2048 + tokv) * 512;
                    float w0 = v0 + bias[n];
                    float w1 = v1 + bias[n + 1];
                    if (n >= dt) w0 = 0.0f;
                    if (n + 1 >= dt) w1 = 0.0f;
                    const float2 xr = *(const float2*)(resid + row + n);
                    float2 o; o.x = xr.x + w0; o.y = xr.y + w1;
                    *(float2*)(g_z + row + n) = o;
                }
            }
        }
    }
    #undef KSTAGE
}

// ---------------- grouped FFN GEMMs (proven R8/R9) ----------------
template<int EPI>
__global__ void __launch_bounds__(256, 2) ggemm_kernel(const float* __restrict__ bias,
                                                       const float* __restrict__ alpha,
                                                       float* __restrict__ outp) {
    const __nv_bfloat16* Aext = (EPI == 2) ? g_hm_ext : g_hid_ext;
    const __nv_bfloat16* Bext = (EPI == 2) ? g_w1_ext : g_w2_ext;
    constexpr int NC  = (EPI == 2) ? 2048 : 512;
    constexpr int SEG = (EPI == 3) ? 2048 : 512;
    constexpr size_t AROW = 3 * SEG;
    constexpr int TN0v = (EPI == 2) ? 2 : 1;
    constexpr int TN1v = (EPI == 2) ? 4 : 1;
    constexpr int TN2v = (EPI == 2) ? 8 : 2;
    constexpr int TN3v = (EPI == 2) ? 16 : 4;
    constexpr int TS3v = (EPI == 3) ? 4 : 1;
    constexpr int TS2v = (EPI == 3) ? 2 : 1;
    constexpr int C3 = 2 * TN3v * TS3v, C2 = 2 * TN2v * TS2v, C1 = 4 * TN1v;

    const int tid = threadIdx.x, lane = tid & 31, wid = tid >> 5;
    const int b = blockIdx.y;
    int idx = blockIdx.x;
    int e, loc, TN, TS;
    if (idx < C3)                 { e = 3; loc = idx;                  TN = TN3v; TS = TS3v; }
    else if (idx < C3 + C2)       { e = 2; loc = idx - C3;             TN = TN2v; TS = TS2v; }
    else if (idx < C3 + C2 + C1)  { e = 1; loc = idx - (C3 + C2);      TN = TN1v; TS = 1; }
    else                          { e = 0; loc = idx - (C3 + C2 + C1); TN = TN0v; TS = 1; }
    const int mt = loc / (TN * TS);
    int rem = loc - mt * (TN * TS);
    const int nt = rem / TS;
    const int sp = rem - nt * TS;
    const int d = 64 << e;
    const int ld = ((EPI == 3) ? 8 : 6) + e;
    const int dm = (1 << ld) - 1;
    const int NStot = (3 << ld) >> 5;
    const int per = NStot / TS;
    const int slab0 = sp * per, slab1 = slab0 + per;
    const int segstart = (e == 0) ? 1024 : (e == 1) ? 512 : (e == 2) ? 256 : 0;

    __shared__ __align__(16) unsigned char smA[2][128 * 64];
    __shared__ __align__(16) unsigned char smB[2][32 * 256];
    __shared__ int sA[128], sT[128];
    if (tid < 128) {
        int pos = segstart + mt * 128 + tid;
        int pv = g_perm[b * 2048 + pos];
        sT[tid] = pv;
        sA[tid] = (EPI == 3) ? (b * 2048 + pos) : (b * 2048 + pv);
    }
    __syncthreads();

    const int rA0 = tid >> 2, cA = tid & 3, rA1 = rA0 + 64;
    const __nv_bfloat16* Ap0 = Aext + (size_t)sA[rA0] * AROW + cA * 8;
    const __nv_bfloat16* Ap1 = Aext + (size_t)sA[rA1] * AROW + cA * 8;
    const int oA0 = rA0 * 64 + ((cA ^ ((rA0 >> 1) & 3)) << 4);
    const int oA1 = rA1 * 64 + ((cA ^ ((rA1 >> 1) & 3)) << 4);
    const int rB0 = tid >> 4, cB = tid & 15, rB1 = rB0 + 16;
    const int bc = nt * 128 + cB * 8;
    const __nv_bfloat16* Bp0 = Bext + (size_t)rB0 * NC + bc;
    const __nv_bfloat16* Bp1 = Bext + (size_t)rB1 * NC + bc;
    const int oB0 = rB0 * 256 + ((cB ^ (rB0 & 7)) << 4);
    const int oB1 = rB1 * 256 + ((cB ^ (rB1 & 7)) << 4);

    const int wm = (wid >> 2) * 64;
    const int widn = wid & 3;

    float acc[4][4][4];
    #pragma unroll
    for (int i = 0; i < 4; i++)
        #pragma unroll
        for (int jx = 0; jx < 4; jx++)
            #pragma unroll
            for (int k = 0; k < 4; k++) acc[i][jx][k] = 0.0f;

    #define GSTAGE(buf, slab) { \
        int kk_ = (slab) * 32; int kb_ = ((kk_ >> ld) * SEG) + (kk_ & dm); \
        uint32_t ba_ = (uint32_t)__cvta_generic_to_shared(smA[buf]); \
        uint32_t bb_ = (uint32_t)__cvta_generic_to_shared(smB[buf]); \
        asm volatile("cp.async.cg.shared.global [%0],[%1],16;\n" :: "r"(ba_ + oA0), "l"(Ap0 + kb_)); \
        asm volatile("cp.async.cg.shared.global [%0],[%1],16;\n" :: "r"(ba_ + oA1), "l"(Ap1 + kb_)); \
        asm volatile("cp.async.cg.shared.global [%0],[%1],16;\n" :: "r"(bb_ + oB0), "l"(Bp0 + (size_t)kb_ * NC)); \
        asm volatile("cp.async.cg.shared.global [%0],[%1],16;\n" :: "r"(bb_ + oB1), "l"(Bp1 + (size_t)kb_ * NC)); \
        asm volatile("cp.async.commit_group;\n"); }

    GSTAGE(0, slab0);

    #pragma unroll 1
    for (int s = slab0; s < slab1; s++) {
        int cur = (s - slab0) & 1;
        if (s + 1 < slab1) {
            GSTAGE(cur ^ 1, s + 1);
            asm volatile("cp.async.wait_group 1;\n");
        } else {
            asm volatile("cp.async.wait_group 0;\n");
        }
        __syncthreads();
        unsigned char* As = smA[cur];
        unsigned char* Bs = smB[cur];
        #pragma unroll
        for (int kk = 0; kk < 2; kk++) {
            uint32_t af[4][4], bfr[4][2];
            #pragma unroll
            for (int mi = 0; mi < 4; mi++) {
                int r = wm + mi * 16 + (lane & 7) + ((lane & 8) ? 8 : 0);
                int c = kk * 2 + ((lane & 16) ? 1 : 0);
                uint32_t sa = (uint32_t)__cvta_generic_to_shared(
                    As + r * 64 + ((c ^ ((r >> 1) & 3)) << 4));
                asm volatile("ldmatrix.sync.aligned.m8n8.x4.shared.b16 {%0,%1,%2,%3},[%4];"
                             : "=r"(af[mi][0]), "=r"(af[mi][1]), "=r"(af[mi][2]), "=r"(af[mi][3])
                             : "r"(sa));
            }
            #pragma unroll
            for (int np = 0; np < 2; np++) {
                int kr = kk * 16 + (lane & 7) + ((lane & 8) ? 8 : 0);
                int c = widn * 4 + np * 2 + ((lane & 16) ? 1 : 0);
                uint32_t sb = (uint32_t)__cvta_generic_to_shared(
                    Bs + kr * 256 + ((c ^ (kr & 7)) << 4));
                asm volatile("ldmatrix.sync.aligned.m8n8.x4.trans.shared.b16 {%0,%1,%2,%3},[%4];"
                             : "=r"(bfr[np * 2][0]), "=r"(bfr[np * 2][1]),
                               "=r"(bfr[np * 2 + 1][0]), "=r"(bfr[np * 2 + 1][1])
                             : "r"(sb));
            }
            #pragma unroll
            for (int mi = 0; mi < 4; mi++)
                #pragma unroll
                for (int ni = 0; ni < 4; ni++)
                    mma16816(acc[mi][ni], af[mi], bfr[ni]);
        }
        __syncthreads();
    }

    const int l4 = lane >> 2, l2 = (lane & 3) * 2;

    if (EPI == 3 && TS > 1) {
        #pragma unroll
        for (int mi = 0; mi < 4; mi++) {
            #pragma unroll
            for (int hh = 0; hh < 2; hh++) {
                int mrl = wm + mi * 16 + l4 + hh * 8;
                int pos = segstart + mt * 128 + mrl;
                #pragma unroll
                for (int ni = 0; ni < 4; ni++) {
                    int n = nt * 128 + widn * 32 + ni * 8 + l2;
                    float2 v; v.x = acc[mi][ni][hh * 2]; v.y = acc[mi][ni][hh * 2 + 1];
                    *(float2*)&g_fpart[sp][((b << 9) + pos) * 512 + n] = v;
                }
            }
        }
        return;
    }

    float aval = 0.0f;
    if (EPI == 3) aval = alpha[0];

    #pragma unroll
    for (int mi = 0; mi < 4; mi++) {
        #pragma unroll
        for (int hh = 0; hh < 2; hh++) {
            int mrl = wm + mi * 16 + l4 + hh * 8;
            int tok = sT[mrl];
            #pragma unroll
            for (int ni = 0; ni < 4; ni++) {
                int n = nt * 128 + widn * 32 + ni * 8 + l2;
                float v0 = acc[mi][ni][hh * 2 + 0];
                float v1 = acc[mi][ni][hh * 2 + 1];
                if (EPI == 2) {
                    if (n < 4 * d) {
                        int pos = segstart + mt * 128 + mrl;
                        size_t row = (size_t)(b * 2048 + pos) * 6144;
                        float w = v0 + bias[n];
                        float c1 = 0.7978845608028654f * (w + 0.044715f * w * w * w);
                        float h0 = 0.5f * w * (1.0f + tanhf(c1));
                        w = v1 + bias[n + 1];
                        c1 = 0.7978845608028654f * (w + 0.044715f * w * w * w);
                        float h1 = 0.5f * w * (1.0f + tanhf(c1));
                        __nv_bfloat16 a0, b0, a1, b1;
                        bsplit(h0, a0, b0); bsplit(h1, a1, b1);
                        __nv_bfloat162 hi; hi.x = a0; hi.y = a1;
                        __nv_bfloat162 lo; lo.x = b0; lo.y = b1;
                        *(__nv_bfloat162*)(g_hid_ext + row + n)        = hi;
                        *(__nv_bfloat162*)(g_hid_ext + row + n + 2048) = hi;
                        *(__nv_bfloat162*)(g_hid_ext + row + n + 4096) = lo;
                    }
                } else {
                    if (n < d) {
                        size_t row = (size_t)(b * 2048 + tok) * 512;
                        float gm = aval * g_rp[b * 2048 + tok] + 1.0f;
                        float w0 = v0 + bias[n];
                        float w1 = v1 + bias[n + 1];
                        const float2 zz = *(const float2*)(g_z + row + n);
                        float2 o; o.x = zz.x + gm * w0; o.y = zz.y + gm * w1;
                        *(float2*)(outp + row + n) = o;
                    }
                }
            }
        }
    }
    #undef GSTAGE
}

__global__ void reduce3_kernel(const float* __restrict__ b2f,
                               const float* __restrict__ alpha,
                               float* __restrict__ outp) {
    int rowid = blockIdx.x;
    int b = rowid >> 9, pos = rowid & 511;
    int ns = (pos < 256) ? 4 : 2;
    int d = (pos < 256) ? 512 : 256;
    int tok = g_perm[b * 2048 + pos];
    float gm = alpha[0] * g_rp[b * 2048 + tok] + 1.0f;
    size_t row = (size_t)(b * 2048 + tok) * 512;
    int base = ((b << 9) + pos) * 512;
    for (int n = threadIdx.x; n < d; n += 256) {
        float s = g_fpart[0][base + n] + g_fpart[1][base + n];
        if (ns == 4) s += g_fpart[2][base + n] + g_fpart[3][base + n];
        s += b2f[n];
        outp[row + n] = g_z[row + n] + gm * s;
    }
}

// ---------------- flash attention: 2-term splits, ext-128 Q/K ----------------
// smem: Q 64x272 + K 64x272 + Vh 64x144 + Vl 64x144 = 53248 B -> 3 CTAs/SM
__global__ void __launch_bounds__(128, 3) fattn_kernel() {
    const int b = blockIdx.y;
    const int slot = blockIdx.x;
    const int h = c_head[slot];
    const int ch = c_chunk[slot];
    extern __shared__ __align__(16) unsigned char sm[];
    unsigned char* Qs  = sm;
    unsigned char* Ks  = sm + 64 * 272;
    unsigned char* Vhs = sm + 2 * 64 * 272;
    unsigned char* Vls = Vhs + 64 * 144;
    __shared__ int tok[64];
    const int tid = threadIdx.x, lane = tid & 31, wid = tid >> 5;

    if (tid < 64) tok[tid] = g_perm[b * N_ + ch * 64 + tid];
    __syncthreads();
    const size_t bh = (size_t)(b * H_ + h) * N_;

    for (int i = tid; i < 64 * 16; i += 128) {
        int r = i >> 4, c = i & 15;
        const __nv_bfloat16* g = g_qext + (bh + tok[r]) * 128 + c * 8;
        uint32_t s = (uint32_t)__cvta_generic_to_shared(Qs + r * 272 + c * 16);
        asm volatile("cp.async.cg.shared.global [%0],[%1],16;\n" :: "r"(s), "l"(g));
    }
    asm volatile("cp.async.commit_group;\n");

    float accO[8][4];
    #pragma unroll
    for (int i = 0; i < 8; i++)
        #pragma unroll
        for (int j = 0; j < 4; j++) accO[i][j] = 0.0f;
    float m0 = -3.0e38f, m1 = -3.0e38f, l0 = 0.0f, l1 = 0.0f;

    const int qrow = wid * 16 + (lane & 15);
    const int krow7 = (lane & 7) + ((lane & 16) ? 8 : 0);
    const int kcsel = ((lane & 8) ? 1 : 0);
    const int vrow7 = (lane & 7) + ((lane & 8) ? 8 : 0);
    const int vcsel = ((lane & 16) ? 1 : 0);

    #pragma unroll 1
    for (int k0 = 0; k0 < N_; k0 += 64) {
        // K tile -> group A
        for (int i = tid; i < 64 * 16; i += 128) {
            int r = i >> 4, c = i & 15;
            const __nv_bfloat16* g = g_kext + (bh + k0 + r) * 128 + c * 8;
            uint32_t s = (uint32_t)__cvta_generic_to_shared(Ks + r * 272 + c * 16);
            asm volatile("cp.async.cg.shared.global [%0],[%1],16;\n" :: "r"(s), "l"(g));
        }
        asm volatile("cp.async.commit_group;\n");
        // V tiles -> group B
        for (int i = tid; i < 64 * 8; i += 128) {
            int r = i >> 3, c = i & 7;
            const __nv_bfloat16* gh = g_vh + (bh + k0 + r) * 64 + c * 8;
            const __nv_bfloat16* gl = g_vl + (bh + k0 + r) * 64 + c * 8;
            uint32_t sh = (uint32_t)__cvta_generic_to_shared(Vhs + r * 144 + c * 16);
            uint32_t sl = (uint32_t)__cvta_generic_to_shared(Vls + r * 144 + c * 16);
            asm volatile("cp.async.cg.shared.global [%0],[%1],16;\n" :: "r"(sh), "l"(gh));
            asm volatile("cp.async.cg.shared.global [%0],[%1],16;\n" :: "r"(sl), "l"(gl));
        }
        asm volatile("cp.async.commit_group;\n");

        asm volatile("cp.async.wait_group 1;\n");
        __syncthreads();

        float S[8][4];
        #pragma unroll
        for (int i = 0; i < 8; i++)
            #pragma unroll
            for (int j = 0; j < 4; j++) S[i][j] = 0.0f;

        #pragma unroll
        for (int ks = 0; ks < 8; ks++) {
            uint32_t qf[4];
            uint32_t sa = (uint32_t)__cvta_generic_to_shared(
                Qs + qrow * 272 + (ks * 2 + (lane >> 4)) * 16);
            asm volatile("ldmatrix.sync.aligned.m8n8.x4.shared.b16 {%0,%1,%2,%3},[%4];"
                         : "=r"(qf[0]), "=r"(qf[1]), "=r"(qf[2]), "=r"(qf[3]) : "r"(sa));
            #pragma unroll
            for (int p = 0; p < 4; p++) {
                uint32_t kf[4];
                uint32_t sb = (uint32_t)__cvta_generic_to_shared(
                    Ks + (p * 16 + krow7) * 272 + (ks * 2 + kcsel) * 16);
                asm volatile("ldmatrix.sync.aligned.m8n8.x4.shared.b16 {%0,%1,%2,%3},[%4];"
                             : "=r"(kf[0]), "=r"(kf[1]), "=r"(kf[2]), "=r"(kf[3]) : "r"(sb));
                mma16816(S[2 * p],     qf, kf);
                mma16816(S[2 * p + 1], qf, kf + 2);
            }
        }

        float mx0 = -3.0e38f, mx1 = -3.0e38f;
        #pragma unroll
        for (int ni = 0; ni < 8; ni++) {
            S[ni][0] *= 0.125f; S[ni][1] *= 0.125f; S[ni][2] *= 0.125f; S[ni][3] *= 0.125f;
            mx0 = fmaxf(mx0, fmaxf(S[ni][0], S[ni][1]));
            mx1 = fmaxf(mx1, fmaxf(S[ni][2], S[ni][3]));
        }
        mx0 = fmaxf(mx0, __shfl_xor_sync(0xffffffffu, mx0, 1));
        mx0 = fmaxf(mx0, __shfl_xor_sync(0xffffffffu, mx0, 2));
        mx1 = fmaxf(mx1, __shfl_xor_sync(0xffffffffu, mx1, 1));
        mx1 = fmaxf(mx1, __shfl_xor_sync(0xffffffffu, mx1, 2));
        float mn0 = fmaxf(m0, mx0), mn1 = fmaxf(m1, mx1);
        float cr0 = __expf(m0 - mn0), cr1 = __expf(m1 - mn1);
        float s0 = 0.0f, s1 = 0.0f;
        uint32_t pha[8], phb[8];
        #pragma unroll
        for (int ni = 0; ni < 8; ni++) {
            float p00 = __expf(S[ni][0] - mn0), p01 = __expf(S[ni][1] - mn0);
            float p10 = __expf(S[ni][2] - mn1), p11 = __expf(S[ni][3] - mn1);
            s0 += p00 + p01; s1 += p10 + p11;
            pha[ni] = packb(__float2bfloat16(p00), __float2bfloat16(p01));
            phb[ni] = packb(__float2bfloat16(p10), __float2bfloat16(p11));
        }
        s0 += __shfl_xor_sync(0xffffffffu, s0, 1);
        s0 += __shfl_xor_sync(0xffffffffu, s0, 2);
        s1 += __shfl_xor_sync(0xffffffffu, s1, 1);
        s1 += __shfl_xor_sync(0xffffffffu, s1, 2);
        l0 = l0 * cr0 + s0; l1 = l1 * cr1 + s1;
        m0 = mn0; m1 = mn1;
        #pragma unroll
        for (int ni = 0; ni < 8; ni++) {
            accO[ni][0] *= cr0; accO[ni][1] *= cr0;
            accO[ni][2] *= cr1; accO[ni][3] *= cr1;
        }

        asm volatile("cp.async.wait_group 0;\n");
        __syncthreads();

        #pragma unroll
        for (int kt = 0; kt < 4; kt++) {
            uint32_t pa[4] = {pha[2 * kt], phb[2 * kt], pha[2 * kt + 1], phb[2 * kt + 1]};
            #pragma unroll
            for (int p = 0; p < 4; p++) {
                uint32_t vh[4], vl[4];
                uint32_t svh = (uint32_t)__cvta_generic_to_shared(
                    Vhs + (kt * 16 + vrow7) * 144 + (p * 2 + vcsel) * 16);
                uint32_t svl = (uint32_t)__cvta_generic_to_shared(
                    Vls + (kt * 16 + vrow7) * 144 + (p * 2 + vcsel) * 16);
                asm volatile("ldmatrix.sync.aligned.m8n8.x4.trans.shared.b16 {%0,%1,%2,%3},[%4];"
                             : "=r"(vh[0]), "=r"(vh[1]), "=r"(vh[2]), "=r"(vh[3]) : "r"(svh));
                asm volatile("ldmatrix.sync.aligned.m8n8.x4.trans.shared.b16 {%0,%1,%2,%3},[%4];"
                             : "=r"(vl[0]), "=r"(vl[1]), "=r"(vl[2]), "=r"(vl[3]) : "r"(svl));
                mma16816(accO[2 * p],     pa, vh);
                mma16816(accO[2 * p + 1], pa, vh + 2);
                mma16816(accO[2 * p],     pa, vl);
                mma16816(accO[2 * p + 1], pa, vl + 2);
            }
        }
        __syncthreads();
    }

    float inv0 = 1.0f / l0, inv1 = 1.0f / l1;
    const int ilo = wid * 16 + (lane >> 2);
    const int ihi = ilo + 8;
    const size_t rlo = (size_t)(b * N_ + tok[ilo]) * 1536 + h * 64 + (lane & 3) * 2;
    const size_t rhi = (size_t)(b * N_ + tok[ihi]) * 1536 + h * 64 + (lane & 3) * 2;
    #pragma unroll
    for (int ni = 0; ni < 8; ni++) {
        float o0 = accO[ni][0] * inv0, o1 = accO[ni][1] * inv0;
        float o2 = accO[ni][2] * inv1, o3 = accO[ni][3] * inv1;
        __nv_bfloat16 h0, q0, h1, q1, h2, q2, h3, q3;
        bsplit(o0, h0, q0); bsplit(o1, h1, q1);
        bsplit(o2, h2, q2); bsplit(o3, h3, q3);
        __nv_bfloat162 hiA; hiA.x = h0; hiA.y = h1;
        __nv_bfloat162 loA; loA.x = q0; loA.y = q1;
        __nv_bfloat162 hiB; hiB.x = h2; hiB.y = h3;
        __nv_bfloat162 loB; loB.x = q2; loB.y = q3;
        *(__nv_bfloat162*)(g_o_ext + rlo + ni * 8)        = hiA;
        *(__nv_bfloat162*)(g_o_ext + rlo + ni * 8 + 512)  = hiA;
        *(__nv_bfloat162*)(g_o_ext + rlo + ni * 8 + 1024) = loA;
        *(__nv_bfloat162*)(g_o_ext + rhi + ni * 8)        = hiB;
        *(__nv_bfloat162*)(g_o_ext + rhi + ni * 8 + 512)  = hiB;
        *(__nv_bfloat162*)(g_o_ext + rhi + ni * 8 + 1024) = loB;
    }
}

__global__ void extras_kernel(float* __restrict__ outp, int write_rp) {
    int i = blockIdx.x * 256 + threadIdx.x;
    if (i < MT) {
        outp[MT * D_ + i] = (float)g_assigned[i];
        if (write_rp) outp[MT * D_ + MT + i] = g_rp[i];
    }
}

extern "C" void kernel_launch(void* const* d_in, const int* in_sizes, int n_in,
                              void* d_out, int out_size) {
    const float* x     = (const float*)d_in[0];
    const float* r_w   = (const float*)d_in[1];
    const float* r_b   = (const float*)d_in[2];
    const float* g1    = (const float*)d_in[3];
    const float* b1    = (const float*)d_in[4];
    const float* g2    = (const float*)d_in[5];
    const float* b2    = (const float*)d_in[6];
    const float* w_qkv = (const float*)d_in[7];
    const float* w_o   = (const float*)d_in[8];
    const float* b_o   = (const float*)d_in[9];
    const float* w1    = (const float*)d_in[10];
    const float* b1f   = (const float*)d_in[11];
    const float* w2    = (const float*)d_in[12];
    const float* b2f   = (const float*)d_in[13];
    const float* alpha = (const float*)d_in[14];
    float* out = (float*)d_out;

    static const int FATTN_SMEM = 2 * 64 * 272 + 2 * 64 * 144;   // 53248
    cudaFuncSetAttribute(fattn_kernel, cudaFuncAttributeMaxDynamicSharedMemorySize, FATTN_SMEM);

    router_kernel<<<MT / 8, 256>>>(x, r_w, r_b);
    assign_kernel<<<B_, 1024>>>();
    wconv_all_kernel<<<3145728 / 256, 256>>>(w_qkv, w_o, w1, w2);

    ln_kernel<0><<<MT / 8, 256>>>(x, g1, b1, nullptr);
    tgk_kernel<0, 1536><<<dim3(12, 64), 256>>>(nullptr, nullptr);
    fattn_kernel<<<dim3(80, B_), 128, FATTN_SMEM>>>();
    tgk_kernel<1, 512><<<dim3(4, 64), 256>>>(b_o, x);
    ln_kernel<1><<<MT / 8, 256>>>(x, g2, b2, out);
    ggemm_kernel<2><<<dim3(80, B_), 256>>>(b1f, nullptr, nullptr);
    ggemm_kernel<3><<<dim3(52, B_), 256>>>(b2f, alpha, out);
    reduce3_kernel<<<B_ * 512, 256>>>(b2f, alpha, out);

    if (out_size >= MT * D_ + MT) {
        int write_rp = (out_size >= MT * D_ + 2 * MT) ? 1 : 0;
        extras_kernel<<<(MT + 255) / 256, 256>>>(out, write_rp);
    }
}